// round 1
// baseline (speedup 1.0000x reference)
#include <cuda_runtime.h>
#include <math.h>

#define Bsz 128
#define Tt  256
#define Hd  1024
#define BT  (Bsz * Tt)

// Scratch (device globals: the sanctioned alloc-free workaround)
__device__ __align__(16) float g_P0[(size_t)BT * Hd];   // x @ Wi0 + bi0 + bh0, all tokens (128 MiB)
__device__ __align__(16) float g_h0[2][Bsz * Hd];       // layer-0 hidden, double buffered by phase parity

// ---------------------------------------------------------------------------
// Precompute: P0[m][n] = sum_k x[m][k] * Wi0[k][n] + bi0[n] + bh0[n]
// M = B*T = 32768, N = H = 1024, K = H = 1024
// Tile 128x128, 256 threads, 8x8 per thread, k-step 8.
// ---------------------------------------------------------------------------
__global__ __launch_bounds__(256) void precompute_kernel(
    const float* __restrict__ x, const float* __restrict__ Wi,
    const float* __restrict__ bi, const float* __restrict__ bh)
{
    __shared__ float xs[8][128];   // [k][m]
    __shared__ float ws[8][128];   // [k][n]

    const int tid = threadIdx.x;
    const int m0 = blockIdx.x * 128;
    const int n0 = blockIdx.y * 128;
    const int tx = tid & 15;       // col group
    const int ty = tid >> 4;       // row group

    // staging indices
    const int lr  = tid >> 1;            // x row 0..127
    const int lk4 = (tid & 1) * 4;       // k chunk 0 or 4
    const int wk  = tid >> 5;            // w k-row 0..7
    const int wn4 = (tid & 31) * 4;      // w col chunk

    float acc[8][8];
#pragma unroll
    for (int i = 0; i < 8; i++)
#pragma unroll
        for (int j = 0; j < 8; j++) acc[i][j] = 0.0f;

    float4 xv = *(const float4*)(x + (size_t)(m0 + lr) * Hd + lk4);
    float4 wv = *(const float4*)(Wi + (size_t)wk * Hd + n0 + wn4);

    for (int k0 = 0; k0 < Hd; k0 += 8) {
        __syncthreads();
        xs[lk4 + 0][lr] = xv.x;
        xs[lk4 + 1][lr] = xv.y;
        xs[lk4 + 2][lr] = xv.z;
        xs[lk4 + 3][lr] = xv.w;
        *(float4*)&ws[wk][wn4] = wv;
        __syncthreads();

        if (k0 + 8 < Hd) {
            xv = *(const float4*)(x + (size_t)(m0 + lr) * Hd + (k0 + 8) + lk4);
            wv = *(const float4*)(Wi + (size_t)(k0 + 8 + wk) * Hd + n0 + wn4);
        }

#pragma unroll
        for (int k = 0; k < 8; k++) {
            float4 a0 = *(const float4*)&xs[k][ty * 4];
            float4 a1 = *(const float4*)&xs[k][64 + ty * 4];
            float4 b0 = *(const float4*)&ws[k][tx * 4];
            float4 b1 = *(const float4*)&ws[k][64 + tx * 4];
            float av[8] = {a0.x, a0.y, a0.z, a0.w, a1.x, a1.y, a1.z, a1.w};
            float bv[8] = {b0.x, b0.y, b0.z, b0.w, b1.x, b1.y, b1.z, b1.w};
#pragma unroll
            for (int i = 0; i < 8; i++)
#pragma unroll
                for (int j = 0; j < 8; j++) acc[i][j] += av[i] * bv[j];
        }
    }

    // bias (layer 0): bi[n] + bh[n]
    float bc[8];
#pragma unroll
    for (int j = 0; j < 8; j++) {
        int n = n0 + (j < 4 ? tx * 4 + j : 64 + tx * 4 + (j - 4));
        bc[j] = bi[n] + bh[n];
    }

#pragma unroll
    for (int i = 0; i < 8; i++) {
        int r = (i < 4) ? (ty * 4 + i) : (64 + ty * 4 + (i - 4));
        float4 o0 = make_float4(acc[i][0] + bc[0], acc[i][1] + bc[1],
                                acc[i][2] + bc[2], acc[i][3] + bc[3]);
        float4 o1 = make_float4(acc[i][4] + bc[4], acc[i][5] + bc[5],
                                acc[i][6] + bc[6], acc[i][7] + bc[7]);
        *(float4*)&g_P0[(size_t)(m0 + r) * Hd + n0 + tx * 4]      = o0;
        *(float4*)&g_P0[(size_t)(m0 + r) * Hd + n0 + 64 + tx * 4] = o1;
    }
}

// ---------------------------------------------------------------------------
// Phase kernel. Phase p (0..T):
//   blocks 0..63  (B-task, active p>=1): h1_{p-1} = tanh(h0_{p-1}@Wi1 + h1_{p-2}@Wh1 + bi1 + bh1)
//                 -> out[:, p-1, :]   (K = 2048 fused)
//   blocks 64..127 (A-task, active p<=T-1): h0_p = tanh(P0[:,p,:] + h0_{p-1}@Wh0)
//                 -> g_h0[p&1]        (K = 1024)
// Tile 128x16, 128 threads, 4x4 per thread, k-step 16.
// ---------------------------------------------------------------------------
struct Src { const float* h; long hs; const float* w; };

__device__ __forceinline__ Src get_src(bool isB, int p, int k0, int n0,
                                       const float* h0in, const float* Wi,
                                       const float* Wh, const float* out)
{
    Src s;
    if (isB) {
        if (k0 < Hd) {
            s.h = g_h0[(p - 1) & 1] + k0; s.hs = Hd;
            s.w = Wi + (size_t)Hd * Hd + (size_t)k0 * Hd + n0;       // Wi1 row k0
        } else {
            int kk = k0 - Hd;
            if (p == 1) { s.h = h0in + Hd + kk; s.hs = 0; }          // layer-1 init, bcast
            else        { s.h = out + (size_t)(p - 2) * Hd + kk; s.hs = (long)Tt * Hd; }
            s.w = Wh + (size_t)Hd * Hd + (size_t)kk * Hd + n0;       // Wh1 row kk
        }
    } else {
        if (p == 0) { s.h = h0in + k0; s.hs = 0; }                   // layer-0 init, bcast
        else        { s.h = g_h0[(p - 1) & 1] + k0; s.hs = Hd; }
        s.w = Wh + (size_t)k0 * Hd + n0;                             // Wh0 row k0
    }
    return s;
}

__global__ __launch_bounds__(128) void phase_kernel(
    int p, const float* __restrict__ h0in, const float* __restrict__ Wi,
    const float* __restrict__ bi, const float* __restrict__ Wh,
    const float* __restrict__ bh, float* __restrict__ out)
{
    const bool isB = (blockIdx.x < 64);
    if (isB && p == 0) return;
    if (!isB && p > Tt - 1) return;

    __shared__ float hs_sh[16][128];   // [k][m]
    __shared__ float ws_sh[16][16];    // [k][n]

    const int tid  = threadIdx.x;
    const int rowg = tid >> 2;         // 0..31
    const int colg = tid & 3;          // 0..3
    const int n0   = (isB ? blockIdx.x : blockIdx.x - 64) * 16;
    const int nK   = isB ? 2 * Hd : Hd;

    float acc[4][4];
#pragma unroll
    for (int i = 0; i < 4; i++)
#pragma unroll
        for (int j = 0; j < 4; j++) acc[i][j] = 0.0f;

    Src s = get_src(isB, p, 0, n0, h0in, Wi, Wh, out);
    float4 hv[4]; float4 wv;
#pragma unroll
    for (int c = 0; c < 4; c++)
        hv[c] = *(const float4*)(s.h + (long)tid * s.hs + c * 4);
    if (tid < 64) wv = *(const float4*)(s.w + (size_t)(tid >> 2) * Hd + (tid & 3) * 4);

    for (int k0 = 0; k0 < nK; k0 += 16) {
        __syncthreads();
#pragma unroll
        for (int c = 0; c < 4; c++) {
            hs_sh[c * 4 + 0][tid] = hv[c].x;
            hs_sh[c * 4 + 1][tid] = hv[c].y;
            hs_sh[c * 4 + 2][tid] = hv[c].z;
            hs_sh[c * 4 + 3][tid] = hv[c].w;
        }
        if (tid < 64) *(float4*)&ws_sh[tid >> 2][(tid & 3) * 4] = wv;
        __syncthreads();

        if (k0 + 16 < nK) {
            s = get_src(isB, p, k0 + 16, n0, h0in, Wi, Wh, out);
#pragma unroll
            for (int c = 0; c < 4; c++)
                hv[c] = *(const float4*)(s.h + (long)tid * s.hs + c * 4);
            if (tid < 64) wv = *(const float4*)(s.w + (size_t)(tid >> 2) * Hd + (tid & 3) * 4);
        }

#pragma unroll
        for (int k = 0; k < 16; k++) {
            float4 a = *(const float4*)&hs_sh[k][rowg * 4];
            float4 b = *(const float4*)&ws_sh[k][colg * 4];
            float av[4] = {a.x, a.y, a.z, a.w};
            float bv[4] = {b.x, b.y, b.z, b.w};
#pragma unroll
            for (int i = 0; i < 4; i++)
#pragma unroll
                for (int j = 0; j < 4; j++) acc[i][j] += av[i] * bv[j];
        }
    }

    if (isB) {
        const int tt = p - 1;
        float bc[4];
#pragma unroll
        for (int j = 0; j < 4; j++) {
            int n = n0 + colg * 4 + j;
            bc[j] = bi[Hd + n] + bh[Hd + n];   // layer-1 combined bias
        }
#pragma unroll
        for (int i = 0; i < 4; i++) {
            int m = rowg * 4 + i;
            float4 o = make_float4(tanhf(acc[i][0] + bc[0]), tanhf(acc[i][1] + bc[1]),
                                   tanhf(acc[i][2] + bc[2]), tanhf(acc[i][3] + bc[3]));
            *(float4*)&out[((size_t)m * Tt + tt) * Hd + n0 + colg * 4] = o;
        }
    } else {
        float* dst = g_h0[p & 1];
#pragma unroll
        for (int i = 0; i < 4; i++) {
            int m = rowg * 4 + i;
            float4 pv = *(const float4*)&g_P0[((size_t)m * Tt + p) * Hd + n0 + colg * 4];
            float4 o = make_float4(tanhf(acc[i][0] + pv.x), tanhf(acc[i][1] + pv.y),
                                   tanhf(acc[i][2] + pv.z), tanhf(acc[i][3] + pv.w));
            *(float4*)&dst[(size_t)m * Hd + n0 + colg * 4] = o;
        }
    }
}

// ---------------------------------------------------------------------------
// Finalize: h_n[b][0][:] = h0_{T-1}, h_n[b][1][:] = h1_{T-1} (= out[:,T-1,:])
// ---------------------------------------------------------------------------
__global__ void finalize_kernel(float* __restrict__ out)
{
    int idx = blockIdx.x * blockDim.x + threadIdx.x;
    if (idx >= Bsz * Hd) return;
    int b = idx / Hd, h = idx % Hd;
    float* hn = out + (size_t)BT * Hd;
    hn[((size_t)b * 2 + 0) * Hd + h] = g_h0[(Tt - 1) & 1][b * Hd + h];
    hn[((size_t)b * 2 + 1) * Hd + h] = out[((size_t)b * Tt + (Tt - 1)) * Hd + h];
}

// ---------------------------------------------------------------------------
extern "C" void kernel_launch(void* const* d_in, const int* in_sizes, int n_in,
                              void* d_out, int out_size)
{
    const float* x    = (const float*)d_in[0];   // [B,T,H]
    const float* h0in = (const float*)d_in[1];   // [1,L,H]
    const float* Wi   = (const float*)d_in[2];   // [L,H,H]
    const float* bi   = (const float*)d_in[3];   // [L,H]
    const float* Wh   = (const float*)d_in[4];   // [L,H,H]
    const float* bh   = (const float*)d_in[5];   // [L,H]
    float* out = (float*)d_out;                  // [B,T,H] then [B,L,H]

    dim3 pgrid(BT / 128, Hd / 128);
    precompute_kernel<<<pgrid, 256>>>(x, Wi, bi, bh);

    for (int p = 0; p <= Tt; ++p)
        phase_kernel<<<128, 128>>>(p, h0in, Wi, bi, Wh, bh, out);

    finalize_kernel<<<(Bsz * Hd + 255) / 256, 256>>>(out);
}

// round 2
// speedup vs baseline: 1.5078x; 1.5078x over previous
#include <cuda_runtime.h>
#include <math.h>

#define Bsz 128
#define Tt  256
#define Hd  1024
#define BT  (Bsz * Tt)

// Scratch (device globals: sanctioned alloc-free workaround)
__device__ __align__(16) float g_P0[(size_t)BT * Hd];   // x@Wi0 + bi0 + bh0 (128 MiB)
__device__ __align__(16) float g_h0[2][Bsz * Hd];       // layer-0 hidden, double buffered
__device__ __align__(16) float g_part[6][Bsz * Hd];     // per-phase GEMM partials (3 MiB)
__device__ int g_cnt[128];                              // tile completion counters (A: 0..63, B: 64..127)

// ---------------------------------------------------------------------------
// Precompute: P0 = x @ Wi0 + bi0 + bh0 over all B*T tokens.
// Tile 128x128, 256 threads, 8x8/thread.
// ---------------------------------------------------------------------------
__global__ __launch_bounds__(256) void precompute_kernel(
    const float* __restrict__ x, const float* __restrict__ Wi,
    const float* __restrict__ bi, const float* __restrict__ bh)
{
    __shared__ float xs[8][128];
    __shared__ float ws[8][128];

    const int tid = threadIdx.x;
    const int m0 = blockIdx.x * 128;
    const int n0 = blockIdx.y * 128;
    const int tx = tid & 15;
    const int ty = tid >> 4;

    const int lr  = tid >> 1;
    const int lk4 = (tid & 1) * 4;
    const int wk  = tid >> 5;
    const int wn4 = (tid & 31) * 4;

    float acc[8][8];
#pragma unroll
    for (int i = 0; i < 8; i++)
#pragma unroll
        for (int j = 0; j < 8; j++) acc[i][j] = 0.0f;

    float4 xv = *(const float4*)(x + (size_t)(m0 + lr) * Hd + lk4);
    float4 wv = *(const float4*)(Wi + (size_t)wk * Hd + n0 + wn4);

    for (int k0 = 0; k0 < Hd; k0 += 8) {
        __syncthreads();
        xs[lk4 + 0][lr] = xv.x;
        xs[lk4 + 1][lr] = xv.y;
        xs[lk4 + 2][lr] = xv.z;
        xs[lk4 + 3][lr] = xv.w;
        *(float4*)&ws[wk][wn4] = wv;
        __syncthreads();

        if (k0 + 8 < Hd) {
            xv = *(const float4*)(x + (size_t)(m0 + lr) * Hd + (k0 + 8) + lk4);
            wv = *(const float4*)(Wi + (size_t)(k0 + 8 + wk) * Hd + n0 + wn4);
        }

#pragma unroll
        for (int k = 0; k < 8; k++) {
            float4 a0 = *(const float4*)&xs[k][ty * 4];
            float4 a1 = *(const float4*)&xs[k][64 + ty * 4];
            float4 b0 = *(const float4*)&ws[k][tx * 4];
            float4 b1 = *(const float4*)&ws[k][64 + tx * 4];
            float av[8] = {a0.x, a0.y, a0.z, a0.w, a1.x, a1.y, a1.z, a1.w};
            float bv[8] = {b0.x, b0.y, b0.z, b0.w, b1.x, b1.y, b1.z, b1.w};
#pragma unroll
            for (int i = 0; i < 8; i++)
#pragma unroll
                for (int j = 0; j < 8; j++) acc[i][j] += av[i] * bv[j];
        }
    }

    float bc[8];
#pragma unroll
    for (int j = 0; j < 8; j++) {
        int n = n0 + (j < 4 ? tx * 4 + j : 64 + tx * 4 + (j - 4));
        bc[j] = bi[n] + bh[n];
    }

#pragma unroll
    for (int i = 0; i < 8; i++) {
        int r = (i < 4) ? (ty * 4 + i) : (64 + ty * 4 + (i - 4));
        float4 o0 = make_float4(acc[i][0] + bc[0], acc[i][1] + bc[1],
                                acc[i][2] + bc[2], acc[i][3] + bc[3]);
        float4 o1 = make_float4(acc[i][4] + bc[4], acc[i][5] + bc[5],
                                acc[i][6] + bc[6], acc[i][7] + bc[7]);
        *(float4*)&g_P0[(size_t)(m0 + r) * Hd + n0 + tx * 4]      = o0;
        *(float4*)&g_P0[(size_t)(m0 + r) * Hd + n0 + 64 + tx * 4] = o1;
    }
}

// ---------------------------------------------------------------------------
// Phase kernel v2. Grid = 384 blocks x 256 threads.
//   part = bid/64 (0..5), tile = bid%64, n0 = tile*16.
//   part 0,1: Gh0 = h0_{p-1} @ Wh0     (K halves 0/1)     [active p <= T-1]
//   part 2,3: Gi1 = h0_{p-1} @ Wi1     (K halves)         [active p >= 1]
//   part 4,5: Gh1 = h1_{p-2} @ Wh1     (K halves)         [active p >= 1]
// Each block: M=128, N=16, K=512; 2 k-groups of 128 threads (named barriers),
// thread tile 4x4; smem reduce across groups; partial -> g_part.
// Last block per tile (atomic counter) sums partials in fixed order,
// adds P0/bias, tanh, writes output. Deterministic values.
// ---------------------------------------------------------------------------
__device__ __forceinline__ void gbar(int id) {
    asm volatile("bar.sync %0, 128;" :: "r"(id) : "memory");
}

__global__ __launch_bounds__(256) void phase_kernel(
    int p, const float* __restrict__ h0in, const float* __restrict__ Wi,
    const float* __restrict__ bi, const float* __restrict__ Wh,
    const float* __restrict__ bh, float* __restrict__ out)
{
    const int part = blockIdx.x >> 6;     // 0..5
    const int tile = blockIdx.x & 63;
    const bool isA = (part < 2);
    if (isA && p >= Tt) return;
    if (!isA && p == 0) return;

    __shared__ float hs[2][16][128];
    __shared__ float ws[2][16][16];
    __shared__ float red[128][17];
    __shared__ int s_old;

    const int tid  = threadIdx.x;
    const int g    = tid & 127;
    const int kg   = tid >> 7;
    const int n0   = tile * 16;
    const int rowg = g >> 2;
    const int colg = g & 3;

    // Resolve sources for this GEMM part
    const float* hbase; long hstr; const float* wbase;
    if (part < 2) {                       // Gh0: h0_{p-1} @ Wh0
        if (p == 0) { hbase = h0in;            hstr = 0;  }
        else        { hbase = g_h0[(p-1) & 1]; hstr = Hd; }
        wbase = Wh;
    } else if (part < 4) {                // Gi1: h0_{p-1} @ Wi1
        hbase = g_h0[(p-1) & 1]; hstr = Hd;
        wbase = Wi + (size_t)Hd * Hd;
    } else {                              // Gh1: h1_{p-2} @ Wh1
        if (p == 1) { hbase = h0in + Hd;                 hstr = 0; }
        else        { hbase = out + (size_t)(p-2) * Hd;  hstr = (long)Tt * Hd; }
        wbase = Wh + (size_t)Hd * Hd;
    }
    const int kstart = (part & 1) * 512 + kg * 256;

    float acc[4][4];
#pragma unroll
    for (int i = 0; i < 4; i++)
#pragma unroll
        for (int j = 0; j < 4; j++) acc[i][j] = 0.0f;

    // Prefetch iter 0
    float4 hv[4]; float4 wv;
    {
        const float* hp = hbase + (long)g * hstr + kstart;
#pragma unroll
        for (int c = 0; c < 4; c++) hv[c] = *(const float4*)(hp + c * 4);
        if (g < 64)
            wv = *(const float4*)(wbase + (size_t)(kstart + (g >> 2)) * Hd + n0 + (g & 3) * 4);
    }

    for (int it = 0; it < 16; ++it) {
        gbar(kg + 1);
#pragma unroll
        for (int c = 0; c < 4; c++) {
            hs[kg][c * 4 + 0][g] = hv[c].x;
            hs[kg][c * 4 + 1][g] = hv[c].y;
            hs[kg][c * 4 + 2][g] = hv[c].z;
            hs[kg][c * 4 + 3][g] = hv[c].w;
        }
        if (g < 64) *(float4*)&ws[kg][g >> 2][(g & 3) * 4] = wv;
        gbar(kg + 1);

        if (it + 1 < 16) {
            const int kt = kstart + (it + 1) * 16;
            const float* hp = hbase + (long)g * hstr + kt;
#pragma unroll
            for (int c = 0; c < 4; c++) hv[c] = *(const float4*)(hp + c * 4);
            if (g < 64)
                wv = *(const float4*)(wbase + (size_t)(kt + (g >> 2)) * Hd + n0 + (g & 3) * 4);
        }

#pragma unroll
        for (int k = 0; k < 16; k++) {
            float4 a = *(const float4*)&hs[kg][k][rowg * 4];
            float4 b = *(const float4*)&ws[kg][k][colg * 4];
            float av[4] = {a.x, a.y, a.z, a.w};
            float bv[4] = {b.x, b.y, b.z, b.w};
#pragma unroll
            for (int i = 0; i < 4; i++)
#pragma unroll
                for (int j = 0; j < 4; j++) acc[i][j] += av[i] * bv[j];
        }
    }

    // Cross-group reduce: kg1 -> smem, kg0 accumulates and stores partial
    if (kg == 1) {
#pragma unroll
        for (int i = 0; i < 4; i++)
#pragma unroll
            for (int j = 0; j < 4; j++) red[g][i * 4 + j] = acc[i][j];
    }
    __syncthreads();
    if (kg == 0) {
        float* mypart = g_part[part];
#pragma unroll
        for (int i = 0; i < 4; i++) {
#pragma unroll
            for (int j = 0; j < 4; j++) acc[i][j] += red[g][i * 4 + j];
            *(float4*)&mypart[(size_t)(rowg * 4 + i) * Hd + n0 + colg * 4] =
                make_float4(acc[i][0], acc[i][1], acc[i][2], acc[i][3]);
        }
    }
    __threadfence();
    __syncthreads();

    const int cidx = isA ? tile : 64 + tile;
    const int need = isA ? 1 : 3;   // arrivals-1
    if (tid == 0) s_old = atomicAdd(&g_cnt[cidx], 1);
    __syncthreads();
    if (s_old != need) return;
    if (tid == 0) g_cnt[cidx] = 0;  // reset for next phase
    __threadfence();                // acquire: see other blocks' partials

    // Epilogue by the last-finishing block: 256 threads x 8 elems
    const int m  = tid >> 1;
    const int c0 = (tid & 1) * 8;
    if (isA) {
        float* dst = g_h0[p & 1];
#pragma unroll
        for (int v = 0; v < 8; v += 4) {
            const int n = n0 + c0 + v;
            float4 a = *(const float4*)&g_part[0][(size_t)m * Hd + n];
            float4 b = *(const float4*)&g_part[1][(size_t)m * Hd + n];
            float4 q = *(const float4*)&g_P0[((size_t)m * Tt + p) * Hd + n];
            float4 o = make_float4(tanhf(a.x + b.x + q.x), tanhf(a.y + b.y + q.y),
                                   tanhf(a.z + b.z + q.z), tanhf(a.w + b.w + q.w));
            *(float4*)&dst[(size_t)m * Hd + n] = o;
        }
    } else {
        const int tt = p - 1;
#pragma unroll
        for (int v = 0; v < 8; v += 4) {
            const int n = n0 + c0 + v;
            float4 s2 = *(const float4*)&g_part[2][(size_t)m * Hd + n];
            float4 s3 = *(const float4*)&g_part[3][(size_t)m * Hd + n];
            float4 s4 = *(const float4*)&g_part[4][(size_t)m * Hd + n];
            float4 s5 = *(const float4*)&g_part[5][(size_t)m * Hd + n];
            float4 b1 = *(const float4*)&bi[Hd + n];
            float4 b2 = *(const float4*)&bh[Hd + n];
            float4 o = make_float4(
                tanhf(s2.x + s3.x + s4.x + s5.x + b1.x + b2.x),
                tanhf(s2.y + s3.y + s4.y + s5.y + b1.y + b2.y),
                tanhf(s2.z + s3.z + s4.z + s5.z + b1.z + b2.z),
                tanhf(s2.w + s3.w + s4.w + s5.w + b1.w + b2.w));
            *(float4*)&out[((size_t)m * Tt + tt) * Hd + n] = o;
        }
    }
}

// ---------------------------------------------------------------------------
// Finalize: h_n[b][0] = h0_{T-1}, h_n[b][1] = h1_{T-1} (= out[:,T-1,:])
// ---------------------------------------------------------------------------
__global__ void finalize_kernel(float* __restrict__ out)
{
    int idx = blockIdx.x * blockDim.x + threadIdx.x;
    if (idx >= Bsz * Hd) return;
    int b = idx / Hd, h = idx % Hd;
    float* hn = out + (size_t)BT * Hd;
    hn[((size_t)b * 2 + 0) * Hd + h] = g_h0[(Tt - 1) & 1][b * Hd + h];
    hn[((size_t)b * 2 + 1) * Hd + h] = out[((size_t)b * Tt + (Tt - 1)) * Hd + h];
}

// ---------------------------------------------------------------------------
extern "C" void kernel_launch(void* const* d_in, const int* in_sizes, int n_in,
                              void* d_out, int out_size)
{
    const float* x    = (const float*)d_in[0];   // [B,T,H]
    const float* h0in = (const float*)d_in[1];   // [1,L,H]
    const float* Wi   = (const float*)d_in[2];   // [L,H,H]
    const float* bi   = (const float*)d_in[3];   // [L,H]
    const float* Wh   = (const float*)d_in[4];   // [L,H,H]
    const float* bh   = (const float*)d_in[5];   // [L,H]
    float* out = (float*)d_out;                  // [B,T,H] then [B,L,H]

    dim3 pgrid(BT / 128, Hd / 128);
    precompute_kernel<<<pgrid, 256>>>(x, Wi, bi, bh);

    for (int p = 0; p <= Tt; ++p)
        phase_kernel<<<384, 256>>>(p, h0in, Wi, bi, Wh, bh, out);

    finalize_kernel<<<(Bsz * Hd + 255) / 256, 256>>>(out);
}

// round 3
// speedup vs baseline: 1.9790x; 1.3125x over previous
#include <cuda_runtime.h>
#include <math.h>

#define Bsz 128
#define Tt  256
#define Hd  1024
#define BT  (Bsz * Tt)

// Scratch (device globals: sanctioned alloc-free workaround)
__device__ __align__(16) float g_P0[(size_t)BT * Hd];   // x@Wi0 + bi0 + bh0 (128 MiB)
__device__ __align__(16) float g_h0[2][Bsz * Hd];       // layer-0 hidden, double buffered
__device__ __align__(16) float g_part[6][Bsz * Hd];     // per-phase GEMM partials
__device__ int g_cnt[32];                               // tile completion counters

// ---------------------------------------------------------------------------
// Precompute: P0 = x @ Wi0 + bi0 + bh0 (fp32 SIMT, unchanged this round)
// ---------------------------------------------------------------------------
__global__ __launch_bounds__(256) void precompute_kernel(
    const float* __restrict__ x, const float* __restrict__ Wi,
    const float* __restrict__ bi, const float* __restrict__ bh)
{
    __shared__ float xs[8][128];
    __shared__ float ws[8][128];

    const int tid = threadIdx.x;
    const int m0 = blockIdx.x * 128;
    const int n0 = blockIdx.y * 128;
    const int tx = tid & 15;
    const int ty = tid >> 4;

    const int lr  = tid >> 1;
    const int lk4 = (tid & 1) * 4;
    const int wk  = tid >> 5;
    const int wn4 = (tid & 31) * 4;

    float acc[8][8];
#pragma unroll
    for (int i = 0; i < 8; i++)
#pragma unroll
        for (int j = 0; j < 8; j++) acc[i][j] = 0.0f;

    float4 xv = *(const float4*)(x + (size_t)(m0 + lr) * Hd + lk4);
    float4 wv = *(const float4*)(Wi + (size_t)wk * Hd + n0 + wn4);

    for (int k0 = 0; k0 < Hd; k0 += 8) {
        __syncthreads();
        xs[lk4 + 0][lr] = xv.x;
        xs[lk4 + 1][lr] = xv.y;
        xs[lk4 + 2][lr] = xv.z;
        xs[lk4 + 3][lr] = xv.w;
        *(float4*)&ws[wk][wn4] = wv;
        __syncthreads();

        if (k0 + 8 < Hd) {
            xv = *(const float4*)(x + (size_t)(m0 + lr) * Hd + (k0 + 8) + lk4);
            wv = *(const float4*)(Wi + (size_t)(k0 + 8 + wk) * Hd + n0 + wn4);
        }

#pragma unroll
        for (int k = 0; k < 8; k++) {
            float4 a0 = *(const float4*)&xs[k][ty * 4];
            float4 a1 = *(const float4*)&xs[k][64 + ty * 4];
            float4 b0 = *(const float4*)&ws[k][tx * 4];
            float4 b1 = *(const float4*)&ws[k][64 + tx * 4];
            float av[8] = {a0.x, a0.y, a0.z, a0.w, a1.x, a1.y, a1.z, a1.w};
            float bv[8] = {b0.x, b0.y, b0.z, b0.w, b1.x, b1.y, b1.z, b1.w};
#pragma unroll
            for (int i = 0; i < 8; i++)
#pragma unroll
                for (int j = 0; j < 8; j++) acc[i][j] += av[i] * bv[j];
        }
    }

    float bc[8];
#pragma unroll
    for (int j = 0; j < 8; j++) {
        int n = n0 + (j < 4 ? tx * 4 + j : 64 + tx * 4 + (j - 4));
        bc[j] = bi[n] + bh[n];
    }

#pragma unroll
    for (int i = 0; i < 8; i++) {
        int r = (i < 4) ? (ty * 4 + i) : (64 + ty * 4 + (i - 4));
        float4 o0 = make_float4(acc[i][0] + bc[0], acc[i][1] + bc[1],
                                acc[i][2] + bc[2], acc[i][3] + bc[3]);
        float4 o1 = make_float4(acc[i][4] + bc[4], acc[i][5] + bc[5],
                                acc[i][6] + bc[6], acc[i][7] + bc[7]);
        *(float4*)&g_P0[(size_t)(m0 + r) * Hd + n0 + tx * 4]      = o0;
        *(float4*)&g_P0[(size_t)(m0 + r) * Hd + n0 + 64 + tx * 4] = o1;
    }
}

// ---------------------------------------------------------------------------
// tf32 helpers
// ---------------------------------------------------------------------------
__device__ __forceinline__ unsigned f2tf(float x) {
    unsigned u;
    asm("cvt.rna.tf32.f32 %0, %1;" : "=r"(u) : "f"(x));
    return u;
}

#define MMA_TF32(C, A, B)                                                     \
    asm volatile(                                                             \
        "mma.sync.aligned.m16n8k8.row.col.f32.tf32.tf32.f32 "                 \
        "{%0,%1,%2,%3}, {%4,%5,%6,%7}, {%8,%9}, {%0,%1,%2,%3};"               \
        : "+f"((C)[0]), "+f"((C)[1]), "+f"((C)[2]), "+f"((C)[3])              \
        : "r"((A).x), "r"((A).y), "r"((A).z), "r"((A).w),                     \
          "r"((B).x), "r"((B).y))

// ---------------------------------------------------------------------------
// Phase kernel v3 (tensor cores). Grid = 96 blocks x 256 threads.
//   part = bid/32: 0=Gh0 (A-task), 1=Gi1, 2=Gh1 (B-task)
//   sub = bid%32: tile = sub>>1 (N-tile of 64), ks = sub&1 (K half of 512)
// Block: M=128, N=64, K=512 via m16n8k8 tf32 mma.
// 8 warps = 4(M) x 2(N); warp tile M=32 x N=32 (2 m-tiles x 4 n-tiles).
// Smem holds fragment-ready tf32 (staged with cvt.rna), k-chunk = 32.
// Partials -> g_part[part*2+ks]; last block per output tile combines,
// adds P0/bias, tanh, writes (deterministic fixed-order sum).
// ---------------------------------------------------------------------------
__global__ __launch_bounds__(256) void phase_kernel(
    int p, const float* __restrict__ h0in, const float* __restrict__ Wi,
    const float* __restrict__ bi, const float* __restrict__ Wh,
    const float* __restrict__ bh, float* __restrict__ out)
{
    const int part = blockIdx.x >> 5;     // 0,1,2
    const int sub  = blockIdx.x & 31;
    const int tile = sub >> 1;            // 0..15
    const int ks   = sub & 1;
    const bool isA = (part == 0);
    if (isA && p >= Tt) return;
    if (!isA && p == 0) return;

    // Fragment-ready smem: As[k8][mtile][lane][reg(4)], Bs[k8][ntile][lane][reg(2)]
    __shared__ unsigned As[4 * 8 * 32 * 4];   // 16 KB
    __shared__ unsigned Bs[4 * 8 * 32 * 2];   // 8 KB
    __shared__ int s_old;

    const int tid  = threadIdx.x;
    const int lane = tid & 31;
    const int wid  = tid >> 5;
    const int wm   = wid & 3;             // M group (rows wm*32)
    const int wn   = wid >> 2;            // N group (cols wn*32)
    const int n0   = tile * 64;
    const int kstart = ks * 512;

    const float* hbase; long hstr; const float* wbase;
    if (part == 0) {                      // Gh0 = h0_{p-1} @ Wh0
        if (p == 0) { hbase = h0in;            hstr = 0;  }
        else        { hbase = g_h0[(p-1) & 1]; hstr = Hd; }
        wbase = Wh;
    } else if (part == 1) {               // Gi1 = h0_{p-1} @ Wi1
        hbase = g_h0[(p-1) & 1]; hstr = Hd;
        wbase = Wi + (size_t)Hd * Hd;
    } else {                              // Gh1 = h1_{p-2} @ Wh1
        if (p == 1) { hbase = h0in + Hd;                hstr = 0; }
        else        { hbase = out + (size_t)(p-2) * Hd; hstr = (long)Tt * Hd; }
        wbase = Wh + (size_t)Hd * Hd;
    }

    float c[2][4][4];
#pragma unroll
    for (int mt = 0; mt < 2; mt++)
#pragma unroll
        for (int nt = 0; nt < 4; nt++)
#pragma unroll
            for (int r = 0; r < 4; r++) c[mt][nt][r] = 0.0f;

    float4 av[4], bv[2];
    // prefetch iter 0
    {
        const int kb = kstart;
#pragma unroll
        for (int i = 0; i < 4; i++) {
            int f = tid + 256 * i, row = f >> 3, c4 = f & 7;
            av[i] = *(const float4*)(hbase + (long)row * hstr + kb + c4 * 4);
        }
#pragma unroll
        for (int i = 0; i < 2; i++) {
            int f = tid + 256 * i, krow = f >> 4, c4 = f & 15;
            bv[i] = *(const float4*)(wbase + (size_t)(kb + krow) * Hd + n0 + c4 * 4);
        }
    }

    for (int it = 0; it < 16; ++it) {
        __syncthreads();
        // --- stage A into fragment layout ---
#pragma unroll
        for (int i = 0; i < 4; i++) {
            int f = tid + 256 * i;
            int row = f >> 3, c4 = f & 7;
            int k8 = c4 >> 1, ch = c4 & 1;       // ch: k-cols 0-3 vs 4-7
            int mtile = row >> 4, r = row & 15;
            int base = ((k8 * 8 + mtile) * 32 + (r & 7) * 4) * 4 + (r >> 3) + ch * 2;
            float vv[4] = {av[i].x, av[i].y, av[i].z, av[i].w};
#pragma unroll
            for (int j = 0; j < 4; j++)          // lane += j -> idx += 4j
                As[base + j * 4] = f2tf(vv[j]);
        }
        // --- stage B into fragment layout ---
#pragma unroll
        for (int i = 0; i < 2; i++) {
            int f = tid + 256 * i;
            int krow = f >> 4, c4 = f & 15;
            int k8 = krow >> 3, kk = krow & 7;
            int ntile = c4 >> 1;
            int base = ((k8 * 8 + ntile) * 32 + (c4 & 1) * 16 + (kk & 3)) * 2 + (kk >> 2);
            float vv[4] = {bv[i].x, bv[i].y, bv[i].z, bv[i].w};
#pragma unroll
            for (int j = 0; j < 4; j++)          // n_in += j -> lane += 4j -> idx += 8j
                Bs[base + j * 8] = f2tf(vv[j]);
        }
        __syncthreads();

        // prefetch next iter (overlaps with mma)
        if (it + 1 < 16) {
            const int kb = kstart + (it + 1) * 32;
#pragma unroll
            for (int i = 0; i < 4; i++) {
                int f = tid + 256 * i, row = f >> 3, c4 = f & 7;
                av[i] = *(const float4*)(hbase + (long)row * hstr + kb + c4 * 4);
            }
#pragma unroll
            for (int i = 0; i < 2; i++) {
                int f = tid + 256 * i, krow = f >> 4, c4 = f & 15;
                bv[i] = *(const float4*)(wbase + (size_t)(kb + krow) * Hd + n0 + c4 * 4);
            }
        }

        // --- compute: 4 k8 steps ---
#pragma unroll
        for (int k8 = 0; k8 < 4; k8++) {
            uint4 a0 = *(const uint4*)&As[((k8 * 8 + 2 * wm + 0) * 32 + lane) * 4];
            uint4 a1 = *(const uint4*)&As[((k8 * 8 + 2 * wm + 1) * 32 + lane) * 4];
            uint2 bfr[4];
#pragma unroll
            for (int nt = 0; nt < 4; nt++)
                bfr[nt] = *(const uint2*)&Bs[((k8 * 8 + 4 * wn + nt) * 32 + lane) * 2];
#pragma unroll
            for (int nt = 0; nt < 4; nt++) {
                MMA_TF32(c[0][nt], a0, bfr[nt]);
                MMA_TF32(c[1][nt], a1, bfr[nt]);
            }
        }
    }

    // --- write partial (this block's K half) ---
    {
        float* mp = g_part[part * 2 + ks];
        const int g = lane >> 2, t = lane & 3;
#pragma unroll
        for (int mt = 0; mt < 2; mt++) {
#pragma unroll
            for (int nt = 0; nt < 4; nt++) {
                int row = wm * 32 + mt * 16 + g;
                int col = n0 + wn * 32 + nt * 8 + 2 * t;
                *(float2*)&mp[(size_t)row * Hd + col] =
                    make_float2(c[mt][nt][0], c[mt][nt][1]);
                *(float2*)&mp[(size_t)(row + 8) * Hd + col] =
                    make_float2(c[mt][nt][2], c[mt][nt][3]);
            }
        }
    }
    __threadfence();
    __syncthreads();

    const int cidx = isA ? tile : 16 + tile;
    const int need = isA ? 1 : 3;       // arrivals - 1
    if (tid == 0) s_old = atomicAdd(&g_cnt[cidx], 1);
    __syncthreads();
    if (s_old != need) return;
    if (tid == 0) g_cnt[cidx] = 0;      // reset for next phase
    __threadfence();                    // acquire other blocks' partials

    // --- epilogue by last-finishing block: 128 rows x 64 cols ---
    const int m  = tid >> 1;
    const int c0 = (tid & 1) * 32;
    if (isA) {
        float* dst = g_h0[p & 1];
#pragma unroll
        for (int v = 0; v < 32; v += 4) {
            const int n = n0 + c0 + v;
            float4 a = *(const float4*)&g_part[0][(size_t)m * Hd + n];
            float4 b = *(const float4*)&g_part[1][(size_t)m * Hd + n];
            float4 q = *(const float4*)&g_P0[((size_t)m * Tt + p) * Hd + n];
            float4 o = make_float4(tanhf(a.x + b.x + q.x), tanhf(a.y + b.y + q.y),
                                   tanhf(a.z + b.z + q.z), tanhf(a.w + b.w + q.w));
            *(float4*)&dst[(size_t)m * Hd + n] = o;
        }
    } else {
        const int tt = p - 1;
#pragma unroll
        for (int v = 0; v < 32; v += 4) {
            const int n = n0 + c0 + v;
            float4 s2 = *(const float4*)&g_part[2][(size_t)m * Hd + n];
            float4 s3 = *(const float4*)&g_part[3][(size_t)m * Hd + n];
            float4 s4 = *(const float4*)&g_part[4][(size_t)m * Hd + n];
            float4 s5 = *(const float4*)&g_part[5][(size_t)m * Hd + n];
            float4 b1 = *(const float4*)&bi[Hd + n];
            float4 b2 = *(const float4*)&bh[Hd + n];
            float4 o = make_float4(
                tanhf(s2.x + s3.x + s4.x + s5.x + b1.x + b2.x),
                tanhf(s2.y + s3.y + s4.y + s5.y + b1.y + b2.y),
                tanhf(s2.z + s3.z + s4.z + s5.z + b1.z + b2.z),
                tanhf(s2.w + s3.w + s4.w + s5.w + b1.w + b2.w));
            *(float4*)&out[((size_t)m * Tt + tt) * Hd + n] = o;
        }
    }
}

// ---------------------------------------------------------------------------
// Finalize: h_n[b][0] = h0_{T-1}, h_n[b][1] = h1_{T-1} (= out[:,T-1,:])
// ---------------------------------------------------------------------------
__global__ void finalize_kernel(float* __restrict__ out)
{
    int idx = blockIdx.x * blockDim.x + threadIdx.x;
    if (idx >= Bsz * Hd) return;
    int b = idx / Hd, h = idx % Hd;
    float* hn = out + (size_t)BT * Hd;
    hn[((size_t)b * 2 + 0) * Hd + h] = g_h0[(Tt - 1) & 1][b * Hd + h];
    hn[((size_t)b * 2 + 1) * Hd + h] = out[((size_t)b * Tt + (Tt - 1)) * Hd + h];
}

// ---------------------------------------------------------------------------
extern "C" void kernel_launch(void* const* d_in, const int* in_sizes, int n_in,
                              void* d_out, int out_size)
{
    const float* x    = (const float*)d_in[0];   // [B,T,H]
    const float* h0in = (const float*)d_in[1];   // [1,L,H]
    const float* Wi   = (const float*)d_in[2];   // [L,H,H]
    const float* bi   = (const float*)d_in[3];   // [L,H]
    const float* Wh   = (const float*)d_in[4];   // [L,H,H]
    const float* bh   = (const float*)d_in[5];   // [L,H]
    float* out = (float*)d_out;                  // [B,T,H] then [B,L,H]

    dim3 pgrid(BT / 128, Hd / 128);
    precompute_kernel<<<pgrid, 256>>>(x, Wi, bi, bh);

    for (int p = 0; p <= Tt; ++p)
        phase_kernel<<<96, 256>>>(p, h0in, Wi, bi, Wh, bh, out);

    finalize_kernel<<<(Bsz * Hd + 255) / 256, 256>>>(out);
}

// round 4
// speedup vs baseline: 4.7750x; 2.4128x over previous
#include <cuda_runtime.h>
#include <math.h>

#define Bsz 128
#define Tt  256
#define Hd  1024
#define BT  (Bsz * Tt)
#define NBLK 96

// Scratch (device globals: sanctioned alloc-free workaround)
__device__ __align__(16) float g_P0[(size_t)BT * Hd];       // x@Wi0 + bi0 + bh0 (128 MiB)
__device__ __align__(16) float g_h0f[Bsz * Hd];             // final h0 (fp32, for finalize)
__device__ __align__(16) float g_part[6][Bsz * Hd];         // per-phase GEMM partials
__device__ __align__(16) unsigned g_h0frag[2][Bsz * Hd];    // h0 in mma-fragment layout, parity buffers
__device__ __align__(16) unsigned g_h1frag[2][Bsz * Hd];    // h1 fragment layout, parity buffers
__device__ int g_cntA[16], g_cntB[16], g_bar;               // tile counters + global phase barrier

// ---------------------------------------------------------------------------
// helpers
// ---------------------------------------------------------------------------
__device__ __forceinline__ unsigned f2tf(float x) {
    unsigned u;
    asm("cvt.rna.tf32.f32 %0, %1;" : "=r"(u) : "f"(x));
    return u;
}

__device__ __forceinline__ int ld_acq(const int* a) {
    int v;
    asm volatile("ld.acquire.gpu.s32 %0, [%1];" : "=r"(v) : "l"(a) : "memory");
    return v;
}

#define MMA_TF32(C, A, B)                                                     \
    asm volatile(                                                             \
        "mma.sync.aligned.m16n8k8.row.col.f32.tf32.tf32.f32 "                 \
        "{%0,%1,%2,%3}, {%4,%5,%6,%7}, {%8,%9}, {%0,%1,%2,%3};"               \
        : "+f"((C)[0]), "+f"((C)[1]), "+f"((C)[2]), "+f"((C)[3])              \
        : "r"((A).x), "r"((A).y), "r"((A).z), "r"((A).w),                     \
          "r"((B).x), "r"((B).y))

// Fragment index of element (row b in 0..127, col n in 0..1023) for m16n8k8 A layout:
// uint index = ((k8*8 + mtile)*32 + lane)*4 + reg
__device__ __forceinline__ int frag_idx(int b, int n) {
    int kc = n & 7;
    int lane = (b & 7) * 4 + (kc & 3);
    int reg  = ((b >> 3) & 1) + ((kc >> 2) << 1);
    return ((((n >> 3) << 3) + (b >> 4)) * 32 + lane) * 4 + reg;
}

// ---------------------------------------------------------------------------
// Init: zero counters, fill initial-state fragment buffers (broadcast h0in rows)
// h0frag[1] <- layer0 init (read at p=0); h1frag[1] <- layer1 init (read at p=1)
// ---------------------------------------------------------------------------
__global__ void init_kernel(const float* __restrict__ h0in)
{
    int idx = blockIdx.x * blockDim.x + threadIdx.x;
    if (idx < 16) { g_cntA[idx] = 0; g_cntB[idx] = 0; }
    if (idx == 16) g_bar = 0;
    for (int e = idx; e < 2 * Bsz * Hd; e += gridDim.x * blockDim.x) {
        int which = e >> 17;            // 0: layer0, 1: layer1
        int r = e & (Bsz * Hd - 1);
        int b = r >> 10, n = r & 1023;
        unsigned v = f2tf(h0in[which * Hd + n]);
        if (which == 0) g_h0frag[1][frag_idx(b, n)] = v;
        else            g_h1frag[1][frag_idx(b, n)] = v;
    }
}

// ---------------------------------------------------------------------------
// Precompute: P0 = x @ Wi0 + bi0 + bh0 (fp32 SIMT, unchanged)
// ---------------------------------------------------------------------------
__global__ __launch_bounds__(256) void precompute_kernel(
    const float* __restrict__ x, const float* __restrict__ Wi,
    const float* __restrict__ bi, const float* __restrict__ bh)
{
    __shared__ float xs[8][128];
    __shared__ float ws[8][128];

    const int tid = threadIdx.x;
    const int m0 = blockIdx.x * 128;
    const int n0 = blockIdx.y * 128;
    const int tx = tid & 15;
    const int ty = tid >> 4;

    const int lr  = tid >> 1;
    const int lk4 = (tid & 1) * 4;
    const int wk  = tid >> 5;
    const int wn4 = (tid & 31) * 4;

    float acc[8][8];
#pragma unroll
    for (int i = 0; i < 8; i++)
#pragma unroll
        for (int j = 0; j < 8; j++) acc[i][j] = 0.0f;

    float4 xv = *(const float4*)(x + (size_t)(m0 + lr) * Hd + lk4);
    float4 wv = *(const float4*)(Wi + (size_t)wk * Hd + n0 + wn4);

    for (int k0 = 0; k0 < Hd; k0 += 8) {
        __syncthreads();
        xs[lk4 + 0][lr] = xv.x;
        xs[lk4 + 1][lr] = xv.y;
        xs[lk4 + 2][lr] = xv.z;
        xs[lk4 + 3][lr] = xv.w;
        *(float4*)&ws[wk][wn4] = wv;
        __syncthreads();

        if (k0 + 8 < Hd) {
            xv = *(const float4*)(x + (size_t)(m0 + lr) * Hd + (k0 + 8) + lk4);
            wv = *(const float4*)(Wi + (size_t)(k0 + 8 + wk) * Hd + n0 + wn4);
        }

#pragma unroll
        for (int k = 0; k < 8; k++) {
            float4 a0 = *(const float4*)&xs[k][ty * 4];
            float4 a1 = *(const float4*)&xs[k][64 + ty * 4];
            float4 b0 = *(const float4*)&ws[k][tx * 4];
            float4 b1 = *(const float4*)&ws[k][64 + tx * 4];
            float av[8] = {a0.x, a0.y, a0.z, a0.w, a1.x, a1.y, a1.z, a1.w};
            float bv[8] = {b0.x, b0.y, b0.z, b0.w, b1.x, b1.y, b1.z, b1.w};
#pragma unroll
            for (int i = 0; i < 8; i++)
#pragma unroll
                for (int j = 0; j < 8; j++) acc[i][j] += av[i] * bv[j];
        }
    }

    float bc[8];
#pragma unroll
    for (int j = 0; j < 8; j++) {
        int n = n0 + (j < 4 ? tx * 4 + j : 64 + tx * 4 + (j - 4));
        bc[j] = bi[n] + bh[n];
    }

#pragma unroll
    for (int i = 0; i < 8; i++) {
        int r = (i < 4) ? (ty * 4 + i) : (64 + ty * 4 + (i - 4));
        float4 o0 = make_float4(acc[i][0] + bc[0], acc[i][1] + bc[1],
                                acc[i][2] + bc[2], acc[i][3] + bc[3]);
        float4 o1 = make_float4(acc[i][4] + bc[4], acc[i][5] + bc[5],
                                acc[i][6] + bc[6], acc[i][7] + bc[7]);
        *(float4*)&g_P0[(size_t)(m0 + r) * Hd + n0 + tx * 4]      = o0;
        *(float4*)&g_P0[(size_t)(m0 + r) * Hd + n0 + 64 + tx * 4] = o1;
    }
}

// ---------------------------------------------------------------------------
// Persistent phase kernel. Grid = 96 blocks x 256 threads, 1 block/SM.
//   part = bid/32 (0=Gh0 [A], 1=Gi1 [B], 2=Gh1 [B]); sub = bid%32;
//   tile = sub>>1 (N-tile of 64), ks = sub&1 (K-half of 512).
// Weights: this block's 512x64 slice loaded ONCE into dynamic smem (128 KB),
// fragment-ready tf32. A-operands: read as ready-made fragments from
// g_h{0,1}frag via __ldcg (L2; parity double-buffered).
// Per phase: MMA -> partial -> tile counter sync -> distributed tanh epilogue
// (writes out / h-frags) -> grid-wide barrier.
// ---------------------------------------------------------------------------
extern __shared__ unsigned Bw[];   // [64 k8][8 ntile][32 lane][2 reg] = 131072 B

__global__ __launch_bounds__(256, 1) void persistent_kernel(
    const float* __restrict__ Wi, const float* __restrict__ bi,
    const float* __restrict__ Wh, const float* __restrict__ bh,
    float* __restrict__ out)
{
    const int part = blockIdx.x >> 5;
    const int sub  = blockIdx.x & 31;
    const int tile = sub >> 1;
    const int ks   = sub & 1;
    const bool isA = (part == 0);

    const int tid  = threadIdx.x;
    const int lane = tid & 31;
    const int wid  = tid >> 5;
    const int wm   = wid & 3;
    const int wn   = wid >> 2;
    const int n0   = tile * 64;
    const int kstart = ks * 512;

    const float* wbase = (part == 0) ? Wh
                       : (part == 1) ? Wi + (size_t)Hd * Hd
                                     : Wh + (size_t)Hd * Hd;

    // ---- one-time weight preload into fragment-ready smem ----
#pragma unroll 4
    for (int i = 0; i < 32; i++) {
        int idx = tid + 256 * i;              // 8192 float4 = 512x64 elements
        int krow = idx >> 4;                  // 0..511
        int c4   = idx & 15;
        float4 w = *(const float4*)(wbase + (size_t)(kstart + krow) * Hd + n0 + c4 * 4);
        int k8 = krow >> 3, kk = krow & 7, ntile = c4 >> 1;
        int base = ((k8 * 8 + ntile) * 32 + (c4 & 1) * 16 + (kk & 3)) * 2 + (kk >> 2);
        Bw[base +  0] = f2tf(w.x);
        Bw[base +  8] = f2tf(w.y);
        Bw[base + 16] = f2tf(w.z);
        Bw[base + 24] = f2tf(w.w);
    }
    __syncthreads();

    for (int p = 0; p <= Tt; ++p) {
        const bool active = isA ? (p < Tt) : (p >= 1);
        if (active) {
            const unsigned* afrag = (part == 2) ? g_h1frag[p & 1]
                                                : g_h0frag[(p - 1) & 1];
            const uint4* abase = ((const uint4*)afrag)
                                 + ((size_t)(ks * 64) * 8 + 2 * wm) * 32 + lane;

            float c[2][4][4];
#pragma unroll
            for (int mt = 0; mt < 2; mt++)
#pragma unroll
                for (int nt = 0; nt < 4; nt++)
#pragma unroll
                    for (int r = 0; r < 4; r++) c[mt][nt][r] = 0.0f;

            uint4 pa[4][2];
#pragma unroll
            for (int i = 0; i < 4; i++) {
                pa[i][0] = __ldcg(abase + i * 256);
                pa[i][1] = __ldcg(abase + i * 256 + 32);
            }

#pragma unroll 4
            for (int k8 = 0; k8 < 64; k8++) {
                int sl = k8 & 3;
                uint4 a0 = pa[sl][0], a1 = pa[sl][1];
                if (k8 < 60) {
                    pa[sl][0] = __ldcg(abase + (k8 + 4) * 256);
                    pa[sl][1] = __ldcg(abase + (k8 + 4) * 256 + 32);
                }
                uint2 bfr[4];
#pragma unroll
                for (int nt = 0; nt < 4; nt++)
                    bfr[nt] = *(const uint2*)&Bw[(((k8 << 3) + 4 * wn + nt) * 32 + lane) * 2];
#pragma unroll
                for (int nt = 0; nt < 4; nt++) {
                    MMA_TF32(c[0][nt], a0, bfr[nt]);
                    MMA_TF32(c[1][nt], a1, bfr[nt]);
                }
            }

            // partial -> global
            {
                float* mp = g_part[part * 2 + ks];
                const int gq = lane >> 2, tq = lane & 3;
#pragma unroll
                for (int mt = 0; mt < 2; mt++)
#pragma unroll
                    for (int nt = 0; nt < 4; nt++) {
                        int row = wm * 32 + mt * 16 + gq;
                        int col = n0 + wn * 32 + nt * 8 + 2 * tq;
                        *(float2*)&mp[(size_t)row * Hd + col] =
                            make_float2(c[mt][nt][0], c[mt][nt][1]);
                        *(float2*)&mp[(size_t)(row + 8) * Hd + col] =
                            make_float2(c[mt][nt][2], c[mt][nt][3]);
                    }
            }

            // tile sync: all blocks of this output tile wait for all partials
            __threadfence();
            __syncthreads();
            if (tid == 0) {
                int* cnt = isA ? &g_cntA[tile] : &g_cntB[tile];
                atomicAdd(cnt, 1);
                const int tgt = isA ? 2 * (p + 1) : 4 * p;
                while (ld_acq(cnt) < tgt) __nanosleep(64);
            }
            __syncthreads();

            // distributed epilogue
            if (isA) {
                const int row = ks * 64 + (tid >> 2);
                const int nb  = n0 + (tid & 3) * 16;
                unsigned* dstf = g_h0frag[p & 1];
#pragma unroll
                for (int v = 0; v < 4; v++) {
                    const int n = nb + v * 4;
                    float4 a = __ldcg((const float4*)&g_part[0][(size_t)row * Hd + n]);
                    float4 b = __ldcg((const float4*)&g_part[1][(size_t)row * Hd + n]);
                    float4 q = __ldcg((const float4*)&g_P0[((size_t)row * Tt + p) * Hd + n]);
                    float r0 = tanhf(a.x + b.x + q.x);
                    float r1 = tanhf(a.y + b.y + q.y);
                    float r2 = tanhf(a.z + b.z + q.z);
                    float r3 = tanhf(a.w + b.w + q.w);
                    if (p == Tt - 1)
                        *(float4*)&g_h0f[(size_t)row * Hd + n] = make_float4(r0, r1, r2, r3);
                    dstf[frag_idx(row, n + 0)] = f2tf(r0);
                    dstf[frag_idx(row, n + 1)] = f2tf(r1);
                    dstf[frag_idx(row, n + 2)] = f2tf(r2);
                    dstf[frag_idx(row, n + 3)] = f2tf(r3);
                }
            } else {
                const int chunk = (part - 1) * 2 + ks;     // 0..3
                const int row = chunk * 32 + (tid >> 3);
                const int nb  = n0 + (tid & 7) * 8;
                const int tt  = p - 1;
                unsigned* dstf = g_h1frag[(p - 1) & 1];
#pragma unroll
                for (int v = 0; v < 2; v++) {
                    const int n = nb + v * 4;
                    float4 s2 = __ldcg((const float4*)&g_part[2][(size_t)row * Hd + n]);
                    float4 s3 = __ldcg((const float4*)&g_part[3][(size_t)row * Hd + n]);
                    float4 s4 = __ldcg((const float4*)&g_part[4][(size_t)row * Hd + n]);
                    float4 s5 = __ldcg((const float4*)&g_part[5][(size_t)row * Hd + n]);
                    float4 b1 = *(const float4*)&bi[Hd + n];
                    float4 b2 = *(const float4*)&bh[Hd + n];
                    float r0 = tanhf(s2.x + s3.x + s4.x + s5.x + b1.x + b2.x);
                    float r1 = tanhf(s2.y + s3.y + s4.y + s5.y + b1.y + b2.y);
                    float r2 = tanhf(s2.z + s3.z + s4.z + s5.z + b1.z + b2.z);
                    float r3 = tanhf(s2.w + s3.w + s4.w + s5.w + b1.w + b2.w);
                    *(float4*)&out[((size_t)row * Tt + tt) * Hd + n] =
                        make_float4(r0, r1, r2, r3);
                    dstf[frag_idx(row, n + 0)] = f2tf(r0);
                    dstf[frag_idx(row, n + 1)] = f2tf(r1);
                    dstf[frag_idx(row, n + 2)] = f2tf(r2);
                    dstf[frag_idx(row, n + 3)] = f2tf(r3);
                }
            }
        }

        // grid-wide phase barrier (all 96 blocks, every phase)
        __threadfence();
        __syncthreads();
        if (tid == 0) {
            atomicAdd(&g_bar, 1);
            const int tgt = NBLK * (p + 1);
            while (ld_acq(&g_bar) < tgt) __nanosleep(64);
        }
        __syncthreads();
    }
}

// ---------------------------------------------------------------------------
// Finalize: h_n[b][0] = h0_{T-1}, h_n[b][1] = h1_{T-1} (= out[:,T-1,:])
// ---------------------------------------------------------------------------
__global__ void finalize_kernel(float* __restrict__ out)
{
    int idx = blockIdx.x * blockDim.x + threadIdx.x;
    if (idx >= Bsz * Hd) return;
    int b = idx / Hd, h = idx % Hd;
    float* hn = out + (size_t)BT * Hd;
    hn[((size_t)b * 2 + 0) * Hd + h] = g_h0f[(size_t)b * Hd + h];
    hn[((size_t)b * 2 + 1) * Hd + h] = out[((size_t)b * Tt + (Tt - 1)) * Hd + h];
}

// ---------------------------------------------------------------------------
extern "C" void kernel_launch(void* const* d_in, const int* in_sizes, int n_in,
                              void* d_out, int out_size)
{
    const float* x    = (const float*)d_in[0];   // [B,T,H]
    const float* h0in = (const float*)d_in[1];   // [1,L,H]
    const float* Wi   = (const float*)d_in[2];   // [L,H,H]
    const float* bi   = (const float*)d_in[3];   // [L,H]
    const float* Wh   = (const float*)d_in[4];   // [L,H,H]
    const float* bh   = (const float*)d_in[5];   // [L,H]
    float* out = (float*)d_out;                  // [B,T,H] then [B,L,H]

    init_kernel<<<256, 256>>>(h0in);

    dim3 pgrid(BT / 128, Hd / 128);
    precompute_kernel<<<pgrid, 256>>>(x, Wi, bi, bh);

    cudaFuncSetAttribute(persistent_kernel,
                         cudaFuncAttributeMaxDynamicSharedMemorySize, 131072);
    persistent_kernel<<<NBLK, 256, 131072>>>(Wi, bi, Wh, bh, out);

    finalize_kernel<<<(Bsz * Hd + 255) / 256, 256>>>(out);
}

// round 5
// speedup vs baseline: 5.2737x; 1.1044x over previous
#include <cuda_runtime.h>
#include <math.h>

#define Bsz 128
#define Tt  256
#define Hd  1024
#define BT  (Bsz * Tt)
#define NBLK 128

// Scratch (device globals: sanctioned alloc-free workaround)
__device__ __align__(16) unsigned g_xfrag[(size_t)BT * Hd]; // x in mma-fragment tf32, per token (128 MiB)
__device__ __align__(16) float g_h0f[Bsz * Hd];             // final h0 (fp32, for finalize)
__device__ __align__(16) float g_part[8][Bsz * Hd];         // per-phase GEMM partials
__device__ __align__(16) unsigned g_h0frag[2][Bsz * Hd];    // h0 fragment layout, parity buffers
__device__ __align__(16) unsigned g_h1frag[2][Bsz * Hd];    // h1 fragment layout, parity buffers
__device__ int g_cntA[16], g_cntB[16], g_bar;               // tile counters + global phase barrier

// ---------------------------------------------------------------------------
// helpers
// ---------------------------------------------------------------------------
__device__ __forceinline__ unsigned f2tf(float x) {
    unsigned u;
    asm("cvt.rna.tf32.f32 %0, %1;" : "=r"(u) : "f"(x));
    return u;
}

__device__ __forceinline__ int ld_acq(const int* a) {
    int v;
    asm volatile("ld.acquire.gpu.s32 %0, [%1];" : "=r"(v) : "l"(a) : "memory");
    return v;
}

#define MMA_TF32(C, A, B)                                                     \
    asm volatile(                                                             \
        "mma.sync.aligned.m16n8k8.row.col.f32.tf32.tf32.f32 "                 \
        "{%0,%1,%2,%3}, {%4,%5,%6,%7}, {%8,%9}, {%0,%1,%2,%3};"               \
        : "+f"((C)[0]), "+f"((C)[1]), "+f"((C)[2]), "+f"((C)[3])              \
        : "r"((A).x), "r"((A).y), "r"((A).z), "r"((A).w),                     \
          "r"((B).x), "r"((B).y))

// Fragment index of element (row b in 0..127, col n in 0..1023), m16n8k8 A layout:
// uint index = ((k8*8 + mtile)*32 + lane)*4 + reg
__device__ __forceinline__ int frag_idx(int b, int n) {
    int kc = n & 7;
    int lane = (b & 7) * 4 + (kc & 3);
    int reg  = ((b >> 3) & 1) + ((kc >> 2) << 1);
    return ((((n >> 3) << 3) + (b >> 4)) * 32 + lane) * 4 + reg;
}

// ---------------------------------------------------------------------------
// Init: zero counters, fill initial-state fragment buffers
// h0frag[1] <- layer0 init (read at p=0); h1frag[1] <- layer1 init (read at p=1)
// ---------------------------------------------------------------------------
__global__ void init_kernel(const float* __restrict__ h0in)
{
    int idx = blockIdx.x * blockDim.x + threadIdx.x;
    if (idx < 16) { g_cntA[idx] = 0; g_cntB[idx] = 0; }
    if (idx == 16) g_bar = 0;
    for (int e = idx; e < 2 * Bsz * Hd; e += gridDim.x * blockDim.x) {
        int which = e >> 17;
        int r = e & (Bsz * Hd - 1);
        int b = r >> 10, n = r & 1023;
        unsigned v = f2tf(h0in[which * Hd + n]);
        if (which == 0) g_h0frag[1][frag_idx(b, n)] = v;
        else            g_h1frag[1][frag_idx(b, n)] = v;
    }
}

// ---------------------------------------------------------------------------
// xprep: convert x [B,T,H] fp32 -> per-token fragment tf32 in g_xfrag.
// Bandwidth-bound one-shot (~256 MB traffic).
// ---------------------------------------------------------------------------
__global__ void xprep_kernel(const float* __restrict__ x)
{
    const int total = BT * Hd / 4;
    for (int e = blockIdx.x * blockDim.x + threadIdx.x; e < total;
         e += gridDim.x * blockDim.x) {
        int n  = (e & 255) * 4;         // Hd/4 = 256 float4 per row
        int bt = e >> 8;                // b*Tt + t
        int b  = bt >> 8;               // Tt = 256
        int t  = bt & 255;
        float4 v = *(const float4*)(x + (size_t)e * 4);
        unsigned* dst = g_xfrag + (size_t)t * (Bsz * Hd);
        dst[frag_idx(b, n + 0)] = f2tf(v.x);
        dst[frag_idx(b, n + 1)] = f2tf(v.y);
        dst[frag_idx(b, n + 2)] = f2tf(v.z);
        dst[frag_idx(b, n + 3)] = f2tf(v.w);
    }
}

// ---------------------------------------------------------------------------
// Persistent kernel. Grid = 128 blocks x 256 threads, 1 block/SM.
//   part = bid/32: 0=Gh0 [A], 1=Gi1 [B], 2=Gh1 [B], 3=Gp=x_p@Wi0 [A-feed]
//   sub = bid%32: tile = sub>>1 (N-tile of 64), ks = sub&1 (K-half of 512).
// Weights: block's 512x64 slice loaded ONCE into 128KB smem, fragment-ready.
// A-operands: ready-made fragments from g_{h0,h1,x}frag via __ldcg.
// Per phase: MMA -> partial -> tile counter (4 arrivals) -> distributed tanh
// epilogue -> grid barrier. A-tile combines Gh0+Gp partials + bias0;
// B-tile combines Gi1+Gh1 partials + bias1.
// ---------------------------------------------------------------------------
extern __shared__ unsigned Bw[];   // [64 k8][8 ntile][32 lane][2 reg] = 131072 B

__global__ __launch_bounds__(256, 1) void persistent_kernel(
    const float* __restrict__ Wi, const float* __restrict__ bi,
    const float* __restrict__ Wh, const float* __restrict__ bh,
    float* __restrict__ out)
{
    const int part = blockIdx.x >> 5;     // 0..3
    const int sub  = blockIdx.x & 31;
    const int tile = sub >> 1;
    const int ks   = sub & 1;
    const bool isA = (part == 0 || part == 3);

    const int tid  = threadIdx.x;
    const int lane = tid & 31;
    const int wid  = tid >> 5;
    const int wm   = wid & 3;
    const int wn   = wid >> 2;
    const int n0   = tile * 64;
    const int kstart = ks * 512;

    const float* wbase = (part == 0) ? Wh
                       : (part == 1) ? Wi + (size_t)Hd * Hd
                       : (part == 2) ? Wh + (size_t)Hd * Hd
                                     : Wi;

    // ---- one-time weight preload into fragment-ready smem ----
#pragma unroll 4
    for (int i = 0; i < 32; i++) {
        int idx = tid + 256 * i;
        int krow = idx >> 4;
        int c4   = idx & 15;
        float4 w = *(const float4*)(wbase + (size_t)(kstart + krow) * Hd + n0 + c4 * 4);
        int k8 = krow >> 3, kk = krow & 7, ntile = c4 >> 1;
        int base = ((k8 * 8 + ntile) * 32 + (c4 & 1) * 16 + (kk & 3)) * 2 + (kk >> 2);
        Bw[base +  0] = f2tf(w.x);
        Bw[base +  8] = f2tf(w.y);
        Bw[base + 16] = f2tf(w.z);
        Bw[base + 24] = f2tf(w.w);
    }
    __syncthreads();

    // partial destination
    float* mp = g_part[(part == 3) ? (6 + ks) : (part * 2 + ks)];

    for (int p = 0; p <= Tt; ++p) {
        const bool active = isA ? (p < Tt) : (p >= 1);
        if (active) {
            const unsigned* afrag =
                (part == 0) ? g_h0frag[(p - 1) & 1] :
                (part == 1) ? g_h0frag[(p - 1) & 1] :
                (part == 2) ? g_h1frag[p & 1]
                            : g_xfrag + (size_t)p * (Bsz * Hd);
            const uint4* abase = ((const uint4*)afrag)
                                 + ((size_t)(ks * 64) * 8 + 2 * wm) * 32 + lane;

            float c[2][4][4];
#pragma unroll
            for (int mt = 0; mt < 2; mt++)
#pragma unroll
                for (int nt = 0; nt < 4; nt++)
#pragma unroll
                    for (int r = 0; r < 4; r++) c[mt][nt][r] = 0.0f;

            uint4 pa[4][2];
#pragma unroll
            for (int i = 0; i < 4; i++) {
                pa[i][0] = __ldcg(abase + i * 256);
                pa[i][1] = __ldcg(abase + i * 256 + 32);
            }

#pragma unroll 4
            for (int k8 = 0; k8 < 64; k8++) {
                int sl = k8 & 3;
                uint4 a0 = pa[sl][0], a1 = pa[sl][1];
                if (k8 < 60) {
                    pa[sl][0] = __ldcg(abase + (k8 + 4) * 256);
                    pa[sl][1] = __ldcg(abase + (k8 + 4) * 256 + 32);
                }
                uint2 bfr[4];
#pragma unroll
                for (int nt = 0; nt < 4; nt++)
                    bfr[nt] = *(const uint2*)&Bw[(((k8 << 3) + 4 * wn + nt) * 32 + lane) * 2];
#pragma unroll
                for (int nt = 0; nt < 4; nt++) {
                    MMA_TF32(c[0][nt], a0, bfr[nt]);
                    MMA_TF32(c[1][nt], a1, bfr[nt]);
                }
            }

            // partial -> global
            {
                const int gq = lane >> 2, tq = lane & 3;
#pragma unroll
                for (int mt = 0; mt < 2; mt++)
#pragma unroll
                    for (int nt = 0; nt < 4; nt++) {
                        int row = wm * 32 + mt * 16 + gq;
                        int col = n0 + wn * 32 + nt * 8 + 2 * tq;
                        *(float2*)&mp[(size_t)row * Hd + col] =
                            make_float2(c[mt][nt][0], c[mt][nt][1]);
                        *(float2*)&mp[(size_t)(row + 8) * Hd + col] =
                            make_float2(c[mt][nt][2], c[mt][nt][3]);
                    }
            }

            // tile sync: 4 blocks contribute to each output tile
            __threadfence();
            __syncthreads();
            if (tid == 0) {
                int* cnt = isA ? &g_cntA[tile] : &g_cntB[tile];
                atomicAdd(cnt, 1);
                const int tgt = isA ? 4 * (p + 1) : 4 * p;
                while (ld_acq(cnt) < tgt) __nanosleep(64);
            }
            __syncthreads();

            // distributed epilogue: 4 blocks/tile, each does 32 rows x 64 cols
            const int chunk = isA ? ((part == 0 ? 0 : 2) + ks)
                                  : ((part - 1) * 2 + ks);
            const int row = chunk * 32 + (tid >> 3);
            const int nb  = n0 + (tid & 7) * 8;
            if (isA) {
                unsigned* dstf = g_h0frag[p & 1];
#pragma unroll
                for (int v = 0; v < 2; v++) {
                    const int n = nb + v * 4;
                    float4 a = __ldcg((const float4*)&g_part[0][(size_t)row * Hd + n]);
                    float4 b = __ldcg((const float4*)&g_part[1][(size_t)row * Hd + n]);
                    float4 q = __ldcg((const float4*)&g_part[6][(size_t)row * Hd + n]);
                    float4 s = __ldcg((const float4*)&g_part[7][(size_t)row * Hd + n]);
                    float4 b1 = *(const float4*)&bi[n];
                    float4 b2 = *(const float4*)&bh[n];
                    float r0 = tanhf(a.x + b.x + q.x + s.x + b1.x + b2.x);
                    float r1 = tanhf(a.y + b.y + q.y + s.y + b1.y + b2.y);
                    float r2 = tanhf(a.z + b.z + q.z + s.z + b1.z + b2.z);
                    float r3 = tanhf(a.w + b.w + q.w + s.w + b1.w + b2.w);
                    if (p == Tt - 1)
                        *(float4*)&g_h0f[(size_t)row * Hd + n] = make_float4(r0, r1, r2, r3);
                    dstf[frag_idx(row, n + 0)] = f2tf(r0);
                    dstf[frag_idx(row, n + 1)] = f2tf(r1);
                    dstf[frag_idx(row, n + 2)] = f2tf(r2);
                    dstf[frag_idx(row, n + 3)] = f2tf(r3);
                }
            } else {
                const int tt = p - 1;
                unsigned* dstf = g_h1frag[(p - 1) & 1];
#pragma unroll
                for (int v = 0; v < 2; v++) {
                    const int n = nb + v * 4;
                    float4 s2 = __ldcg((const float4*)&g_part[2][(size_t)row * Hd + n]);
                    float4 s3 = __ldcg((const float4*)&g_part[3][(size_t)row * Hd + n]);
                    float4 s4 = __ldcg((const float4*)&g_part[4][(size_t)row * Hd + n]);
                    float4 s5 = __ldcg((const float4*)&g_part[5][(size_t)row * Hd + n]);
                    float4 b1 = *(const float4*)&bi[Hd + n];
                    float4 b2 = *(const float4*)&bh[Hd + n];
                    float r0 = tanhf(s2.x + s3.x + s4.x + s5.x + b1.x + b2.x);
                    float r1 = tanhf(s2.y + s3.y + s4.y + s5.y + b1.y + b2.y);
                    float r2 = tanhf(s2.z + s3.z + s4.z + s5.z + b1.z + b2.z);
                    float r3 = tanhf(s2.w + s3.w + s4.w + s5.w + b1.w + b2.w);
                    *(float4*)&out[((size_t)row * Tt + tt) * Hd + n] =
                        make_float4(r0, r1, r2, r3);
                    dstf[frag_idx(row, n + 0)] = f2tf(r0);
                    dstf[frag_idx(row, n + 1)] = f2tf(r1);
                    dstf[frag_idx(row, n + 2)] = f2tf(r2);
                    dstf[frag_idx(row, n + 3)] = f2tf(r3);
                }
            }
        }

        // grid-wide phase barrier
        __threadfence();
        __syncthreads();
        if (tid == 0) {
            atomicAdd(&g_bar, 1);
            const int tgt = NBLK * (p + 1);
            while (ld_acq(&g_bar) < tgt) __nanosleep(64);
        }
        __syncthreads();
    }
}

// ---------------------------------------------------------------------------
// Finalize: h_n[b][0] = h0_{T-1}, h_n[b][1] = h1_{T-1} (= out[:,T-1,:])
// ---------------------------------------------------------------------------
__global__ void finalize_kernel(float* __restrict__ out)
{
    int idx = blockIdx.x * blockDim.x + threadIdx.x;
    if (idx >= Bsz * Hd) return;
    int b = idx / Hd, h = idx % Hd;
    float* hn = out + (size_t)BT * Hd;
    hn[((size_t)b * 2 + 0) * Hd + h] = g_h0f[(size_t)b * Hd + h];
    hn[((size_t)b * 2 + 1) * Hd + h] = out[((size_t)b * Tt + (Tt - 1)) * Hd + h];
}

// ---------------------------------------------------------------------------
extern "C" void kernel_launch(void* const* d_in, const int* in_sizes, int n_in,
                              void* d_out, int out_size)
{
    const float* x    = (const float*)d_in[0];   // [B,T,H]
    const float* h0in = (const float*)d_in[1];   // [1,L,H]
    const float* Wi   = (const float*)d_in[2];   // [L,H,H]
    const float* bi   = (const float*)d_in[3];   // [L,H]
    const float* Wh   = (const float*)d_in[4];   // [L,H,H]
    const float* bh   = (const float*)d_in[5];   // [L,H]
    float* out = (float*)d_out;                  // [B,T,H] then [B,L,H]

    init_kernel<<<256, 256>>>(h0in);
    xprep_kernel<<<8192, 256>>>(x);

    cudaFuncSetAttribute(persistent_kernel,
                         cudaFuncAttributeMaxDynamicSharedMemorySize, 131072);
    persistent_kernel<<<NBLK, 256, 131072>>>(Wi, bi, Wh, bh, out);

    finalize_kernel<<<(Bsz * Hd + 255) / 256, 256>>>(out);
}

// round 6
// speedup vs baseline: 6.6657x; 1.2640x over previous
#include <cuda_runtime.h>
#include <math.h>

#define Bsz 128
#define Tt  256
#define Hd  1024
#define BT  (Bsz * Tt)
#define NBLK 128

// Scratch (device globals: sanctioned alloc-free workaround)
__device__ __align__(16) unsigned g_xfrag[(size_t)BT * Hd]; // x as mma-fragment tf32 per token (128 MiB)
__device__ __align__(16) float g_h0f[Bsz * Hd];             // final h0 (fp32, for finalize)
__device__ __align__(16) float g_part[8][Bsz * Hd];         // per-phase GEMM partials
__device__ __align__(16) unsigned g_h0frag[2][Bsz * Hd];    // h0 fragment layout, parity buffers
__device__ __align__(16) unsigned g_h1frag[2][Bsz * Hd];    // h1 fragment layout, parity buffers
__device__ int g_cntA[16], g_cntB[16], g_bar;               // tile counters + global phase barrier

// ---------------------------------------------------------------------------
// helpers
// ---------------------------------------------------------------------------
__device__ __forceinline__ unsigned f2tf(float x) {
    unsigned u;
    asm("cvt.rna.tf32.f32 %0, %1;" : "=r"(u) : "f"(x));
    return u;
}

__device__ __forceinline__ int ld_acq(const int* a) {
    int v;
    asm volatile("ld.acquire.gpu.s32 %0, [%1];" : "=r"(v) : "l"(a) : "memory");
    return v;
}

__device__ __forceinline__ void prefetchL2(const void* p) {
    asm volatile("prefetch.global.L2 [%0];" :: "l"(p));
}

#define MMA_TF32(C, A, B)                                                     \
    asm volatile(                                                             \
        "mma.sync.aligned.m16n8k8.row.col.f32.tf32.tf32.f32 "                 \
        "{%0,%1,%2,%3}, {%4,%5,%6,%7}, {%8,%9}, {%0,%1,%2,%3};"               \
        : "+f"((C)[0]), "+f"((C)[1]), "+f"((C)[2]), "+f"((C)[3])              \
        : "r"((A).x), "r"((A).y), "r"((A).z), "r"((A).w),                     \
          "r"((B).x), "r"((B).y))

// Fragment index of element (row b in 0..127, col n in 0..1023), m16n8k8 A layout:
// uint index = ((k8*8 + mtile)*32 + lane)*4 + reg
__device__ __forceinline__ int frag_idx(int b, int n) {
    int kc = n & 7;
    int lane = (b & 7) * 4 + (kc & 3);
    int reg  = ((b >> 3) & 1) + ((kc >> 2) << 1);
    return ((((n >> 3) << 3) + (b >> 4)) * 32 + lane) * 4 + reg;
}

// ---------------------------------------------------------------------------
// Init: zero counters, fill initial-state fragment buffers
// ---------------------------------------------------------------------------
__global__ void init_kernel(const float* __restrict__ h0in)
{
    int idx = blockIdx.x * blockDim.x + threadIdx.x;
    if (idx < 16) { g_cntA[idx] = 0; g_cntB[idx] = 0; }
    if (idx == 16) g_bar = 0;
    for (int e = idx; e < 2 * Bsz * Hd; e += gridDim.x * blockDim.x) {
        int which = e >> 17;
        int r = e & (Bsz * Hd - 1);
        int b = r >> 10, n = r & 1023;
        unsigned v = f2tf(h0in[which * Hd + n]);
        if (which == 0) g_h0frag[1][frag_idx(b, n)] = v;
        else            g_h1frag[1][frag_idx(b, n)] = v;
    }
}

// ---------------------------------------------------------------------------
// xprep: x [B,T,H] fp32 -> per-token fragment tf32 in g_xfrag (one-shot).
// ---------------------------------------------------------------------------
__global__ void xprep_kernel(const float* __restrict__ x)
{
    const int total = BT * Hd / 4;
    for (int e = blockIdx.x * blockDim.x + threadIdx.x; e < total;
         e += gridDim.x * blockDim.x) {
        int n  = (e & 255) * 4;
        int bt = e >> 8;
        int b  = bt >> 8;
        int t  = bt & 255;
        float4 v = *(const float4*)(x + (size_t)e * 4);
        unsigned* dst = g_xfrag + (size_t)t * (Bsz * Hd);
        dst[frag_idx(b, n + 0)] = f2tf(v.x);
        dst[frag_idx(b, n + 1)] = f2tf(v.y);
        dst[frag_idx(b, n + 2)] = f2tf(v.z);
        dst[frag_idx(b, n + 3)] = f2tf(v.w);
    }
}

// ---------------------------------------------------------------------------
// Persistent kernel. Grid = 128 blocks x 512 threads (16 warps), 1 block/SM.
//   part = bid/32: 0=Gh0 [A], 1=Gi1 [B], 2=Gh1 [B], 3=Gp=x_p@Wi0 [A-feed]
//   sub = bid%32: tile = sub>>1 (N-tile of 64), ks = sub&1 (K-half of 512).
// Warp layout: wm = wid&7 (M-tile of 16), wn = wid>>3 (N-group of 32).
// Weights in 128KB fragment-ready smem (loaded once). A-fragments via __ldcg
// with depth-8 prefetch; part-3 additionally L2-prefetches phase p+1's x.
// ---------------------------------------------------------------------------
extern __shared__ unsigned Bw[];   // [64 k8][8 ntile][32 lane][2 reg] = 131072 B

__global__ __launch_bounds__(512, 1) void persistent_kernel(
    const float* __restrict__ Wi, const float* __restrict__ bi,
    const float* __restrict__ Wh, const float* __restrict__ bh,
    float* __restrict__ out)
{
    const int part = blockIdx.x >> 5;     // 0..3
    const int sub  = blockIdx.x & 31;
    const int tile = sub >> 1;
    const int ks   = sub & 1;
    const bool isA = (part == 0 || part == 3);

    const int tid  = threadIdx.x;
    const int lane = tid & 31;
    const int wid  = tid >> 5;
    const int wm   = wid & 7;             // M-tile (16 rows)
    const int wn   = wid >> 3;            // N-group (32 cols)
    const int n0   = tile * 64;
    const int kstart = ks * 512;

    const float* wbase = (part == 0) ? Wh
                       : (part == 1) ? Wi + (size_t)Hd * Hd
                       : (part == 2) ? Wh + (size_t)Hd * Hd
                                     : Wi;

    // ---- one-time weight preload into fragment-ready smem ----
#pragma unroll 4
    for (int i = 0; i < 16; i++) {
        int idx = tid + 512 * i;              // 8192 float4 = 512x64 elements
        int krow = idx >> 4;
        int c4   = idx & 15;
        float4 w = *(const float4*)(wbase + (size_t)(kstart + krow) * Hd + n0 + c4 * 4);
        int k8 = krow >> 3, kk = krow & 7, ntile = c4 >> 1;
        int base = ((k8 * 8 + ntile) * 32 + (c4 & 1) * 16 + (kk & 3)) * 2 + (kk >> 2);
        Bw[base +  0] = f2tf(w.x);
        Bw[base +  8] = f2tf(w.y);
        Bw[base + 16] = f2tf(w.z);
        Bw[base + 24] = f2tf(w.w);
    }
    __syncthreads();

    float* mp = g_part[(part == 3) ? (6 + ks) : (part * 2 + ks)];

    for (int p = 0; p <= Tt; ++p) {
        const bool active = isA ? (p < Tt) : (p >= 1);
        if (active) {
            const unsigned* afrag =
                (part == 0) ? g_h0frag[(p - 1) & 1] :
                (part == 1) ? g_h0frag[(p - 1) & 1] :
                (part == 2) ? g_h1frag[p & 1]
                            : g_xfrag + (size_t)p * (Bsz * Hd);
            const uint4* abase = ((const uint4*)afrag)
                                 + ((size_t)(ks * 64) * 8 + wm) * 32 + lane;

            float c[4][4];
#pragma unroll
            for (int nt = 0; nt < 4; nt++)
#pragma unroll
                for (int r = 0; r < 4; r++) c[nt][r] = 0.0f;

            uint4 pa[8];
#pragma unroll
            for (int i = 0; i < 8; i++)
                pa[i] = __ldcg(abase + i * 256);

#pragma unroll 8
            for (int k8 = 0; k8 < 64; k8++) {
                uint4 a = pa[k8 & 7];
                if (k8 < 56)
                    pa[k8 & 7] = __ldcg(abase + (k8 + 8) * 256);
                uint2 bfr[4];
#pragma unroll
                for (int nt = 0; nt < 4; nt++)
                    bfr[nt] = *(const uint2*)&Bw[(((k8 << 3) + wn * 4 + nt) * 32 + lane) * 2];
#pragma unroll
                for (int nt = 0; nt < 4; nt++)
                    MMA_TF32(c[nt], a, bfr[nt]);
            }

            // partial -> global
            {
                const int gq = lane >> 2, tq = lane & 3;
#pragma unroll
                for (int nt = 0; nt < 4; nt++) {
                    int row = wm * 16 + gq;
                    int col = n0 + wn * 32 + nt * 8 + 2 * tq;
                    *(float2*)&mp[(size_t)row * Hd + col] =
                        make_float2(c[nt][0], c[nt][1]);
                    *(float2*)&mp[(size_t)(row + 8) * Hd + col] =
                        make_float2(c[nt][2], c[nt][3]);
                }
            }

            // L2-prefetch next phase's x slice (part 3 only) while others finish
            if (part == 3 && p + 1 < Tt && wn == 0 && (lane & 7) == 0) {
                const uint4* nb = ((const uint4*)(g_xfrag + (size_t)(p + 1) * (Bsz * Hd)))
                                  + ((size_t)(ks * 64) * 8 + wm) * 32 + lane;
#pragma unroll 8
                for (int k8 = 0; k8 < 64; k8++)
                    prefetchL2(nb + k8 * 256);
            }

            // tile sync: 4 blocks contribute to each output tile
            __threadfence();
            __syncthreads();
            if (tid == 0) {
                int* cnt = isA ? &g_cntA[tile] : &g_cntB[tile];
                atomicAdd(cnt, 1);
                const int tgt = isA ? 4 * (p + 1) : 4 * p;
                while (ld_acq(cnt) < tgt) __nanosleep(64);
            }
            __syncthreads();

            // distributed epilogue: 4 blocks/tile, each 32 rows x 64 cols,
            // 512 threads -> one float4 per thread
            const int chunk = isA ? ((part == 0 ? 0 : 2) + ks)
                                  : ((part - 1) * 2 + ks);
            const int row = chunk * 32 + (tid >> 4);
            const int n   = n0 + (tid & 15) * 4;
            if (isA) {
                unsigned* dstf = g_h0frag[p & 1];
                float4 a = __ldcg((const float4*)&g_part[0][(size_t)row * Hd + n]);
                float4 b = __ldcg((const float4*)&g_part[1][(size_t)row * Hd + n]);
                float4 q = __ldcg((const float4*)&g_part[6][(size_t)row * Hd + n]);
                float4 s = __ldcg((const float4*)&g_part[7][(size_t)row * Hd + n]);
                float4 b1 = *(const float4*)&bi[n];
                float4 b2 = *(const float4*)&bh[n];
                float r0 = tanhf(a.x + b.x + q.x + s.x + b1.x + b2.x);
                float r1 = tanhf(a.y + b.y + q.y + s.y + b1.y + b2.y);
                float r2 = tanhf(a.z + b.z + q.z + s.z + b1.z + b2.z);
                float r3 = tanhf(a.w + b.w + q.w + s.w + b1.w + b2.w);
                if (p == Tt - 1)
                    *(float4*)&g_h0f[(size_t)row * Hd + n] = make_float4(r0, r1, r2, r3);
                dstf[frag_idx(row, n + 0)] = f2tf(r0);
                dstf[frag_idx(row, n + 1)] = f2tf(r1);
                dstf[frag_idx(row, n + 2)] = f2tf(r2);
                dstf[frag_idx(row, n + 3)] = f2tf(r3);
            } else {
                const int tt = p - 1;
                unsigned* dstf = g_h1frag[(p - 1) & 1];
                float4 s2 = __ldcg((const float4*)&g_part[2][(size_t)row * Hd + n]);
                float4 s3 = __ldcg((const float4*)&g_part[3][(size_t)row * Hd + n]);
                float4 s4 = __ldcg((const float4*)&g_part[4][(size_t)row * Hd + n]);
                float4 s5 = __ldcg((const float4*)&g_part[5][(size_t)row * Hd + n]);
                float4 b1 = *(const float4*)&bi[Hd + n];
                float4 b2 = *(const float4*)&bh[Hd + n];
                float r0 = tanhf(s2.x + s3.x + s4.x + s5.x + b1.x + b2.x);
                float r1 = tanhf(s2.y + s3.y + s4.y + s5.y + b1.y + b2.y);
                float r2 = tanhf(s2.z + s3.z + s4.z + s5.z + b1.z + b2.z);
                float r3 = tanhf(s2.w + s3.w + s4.w + s5.w + b1.w + b2.w);
                *(float4*)&out[((size_t)row * Tt + tt) * Hd + n] =
                    make_float4(r0, r1, r2, r3);
                dstf[frag_idx(row, n + 0)] = f2tf(r0);
                dstf[frag_idx(row, n + 1)] = f2tf(r1);
                dstf[frag_idx(row, n + 2)] = f2tf(r2);
                dstf[frag_idx(row, n + 3)] = f2tf(r3);
            }
        }

        // grid-wide phase barrier
        __threadfence();
        __syncthreads();
        if (tid == 0) {
            atomicAdd(&g_bar, 1);
            const int tgt = NBLK * (p + 1);
            while (ld_acq(&g_bar) < tgt) __nanosleep(64);
        }
        __syncthreads();
    }
}

// ---------------------------------------------------------------------------
// Finalize: h_n[b][0] = h0_{T-1}, h_n[b][1] = h1_{T-1} (= out[:,T-1,:])
// ---------------------------------------------------------------------------
__global__ void finalize_kernel(float* __restrict__ out)
{
    int idx = blockIdx.x * blockDim.x + threadIdx.x;
    if (idx >= Bsz * Hd) return;
    int b = idx / Hd, h = idx % Hd;
    float* hn = out + (size_t)BT * Hd;
    hn[((size_t)b * 2 + 0) * Hd + h] = g_h0f[(size_t)b * Hd + h];
    hn[((size_t)b * 2 + 1) * Hd + h] = out[((size_t)b * Tt + (Tt - 1)) * Hd + h];
}

// ---------------------------------------------------------------------------
extern "C" void kernel_launch(void* const* d_in, const int* in_sizes, int n_in,
                              void* d_out, int out_size)
{
    const float* x    = (const float*)d_in[0];   // [B,T,H]
    const float* h0in = (const float*)d_in[1];   // [1,L,H]
    const float* Wi   = (const float*)d_in[2];   // [L,H,H]
    const float* bi   = (const float*)d_in[3];   // [L,H]
    const float* Wh   = (const float*)d_in[4];   // [L,H,H]
    const float* bh   = (const float*)d_in[5];   // [L,H]
    float* out = (float*)d_out;                  // [B,T,H] then [B,L,H]

    init_kernel<<<256, 256>>>(h0in);
    xprep_kernel<<<8192, 256>>>(x);

    cudaFuncSetAttribute(persistent_kernel,
                         cudaFuncAttributeMaxDynamicSharedMemorySize, 131072);
    persistent_kernel<<<NBLK, 512, 131072>>>(Wi, bi, Wh, bh, out);

    finalize_kernel<<<(Bsz * Hd + 255) / 256, 256>>>(out);
}

// round 7
// speedup vs baseline: 6.7657x; 1.0150x over previous
#include <cuda_runtime.h>
#include <math.h>

#define Bsz 128
#define Tt  256
#define Hd  1024
#define BT  (Bsz * Tt)

// Scratch (device globals: sanctioned alloc-free workaround)
__device__ __align__(16) unsigned g_xfrag[(size_t)BT * Hd]; // x as mma-fragment tf32 per token (128 MiB)
__device__ __align__(16) float g_h0f[Bsz * Hd];             // final h0 (fp32, for finalize)
__device__ __align__(16) float g_part[8][Bsz * Hd];         // per-phase GEMM partials
__device__ __align__(16) unsigned g_h0frag[2][Bsz * Hd];    // h0 fragment layout, parity buffers
__device__ __align__(16) unsigned g_h1frag[2][Bsz * Hd];    // h1 fragment layout, parity buffers
__device__ int g_cntA[16], g_cntB[16];                      // tile completion counters (monotonic)
__device__ int g_barA, g_barB;                              // group phase barriers (monotonic)

// ---------------------------------------------------------------------------
// helpers
// ---------------------------------------------------------------------------
__device__ __forceinline__ unsigned f2tf(float x) {
    unsigned u;
    asm("cvt.rna.tf32.f32 %0, %1;" : "=r"(u) : "f"(x));
    return u;
}

__device__ __forceinline__ int ld_acq(const int* a) {
    int v;
    asm volatile("ld.acquire.gpu.s32 %0, [%1];" : "=r"(v) : "l"(a) : "memory");
    return v;
}

__device__ __forceinline__ void prefetchL2(const void* p) {
    asm volatile("prefetch.global.L2 [%0];" :: "l"(p));
}

#define MMA_TF32(C, A, B)                                                     \
    asm volatile(                                                             \
        "mma.sync.aligned.m16n8k8.row.col.f32.tf32.tf32.f32 "                 \
        "{%0,%1,%2,%3}, {%4,%5,%6,%7}, {%8,%9}, {%0,%1,%2,%3};"               \
        : "+f"((C)[0]), "+f"((C)[1]), "+f"((C)[2]), "+f"((C)[3])              \
        : "r"((A).x), "r"((A).y), "r"((A).z), "r"((A).w),                     \
          "r"((B).x), "r"((B).y))

// Fragment index of element (row b in 0..127, col n in 0..1023), m16n8k8 A layout:
// uint index = ((k8*8 + mtile)*32 + lane)*4 + reg
__device__ __forceinline__ int frag_idx(int b, int n) {
    int kc = n & 7;
    int lane = (b & 7) * 4 + (kc & 3);
    int reg  = ((b >> 3) & 1) + ((kc >> 2) << 1);
    return ((((n >> 3) << 3) + (b >> 4)) * 32 + lane) * 4 + reg;
}

// ---------------------------------------------------------------------------
// Init: zero counters, fill initial-state fragment buffers
// ---------------------------------------------------------------------------
__global__ void init_kernel(const float* __restrict__ h0in)
{
    int idx = blockIdx.x * blockDim.x + threadIdx.x;
    if (idx < 16) { g_cntA[idx] = 0; g_cntB[idx] = 0; }
    if (idx == 16) { g_barA = 0; g_barB = 0; }
    for (int e = idx; e < 2 * Bsz * Hd; e += gridDim.x * blockDim.x) {
        int which = e >> 17;
        int r = e & (Bsz * Hd - 1);
        int b = r >> 10, n = r & 1023;
        unsigned v = f2tf(h0in[which * Hd + n]);
        if (which == 0) g_h0frag[1][frag_idx(b, n)] = v;
        else            g_h1frag[1][frag_idx(b, n)] = v;
    }
}

// ---------------------------------------------------------------------------
// xprep: x [B,T,H] fp32 -> per-token fragment tf32 in g_xfrag (one-shot).
// ---------------------------------------------------------------------------
__global__ void xprep_kernel(const float* __restrict__ x)
{
    const int total = BT * Hd / 4;
    for (int e = blockIdx.x * blockDim.x + threadIdx.x; e < total;
         e += gridDim.x * blockDim.x) {
        int n  = (e & 255) * 4;
        int bt = e >> 8;
        int b  = bt >> 8;
        int t  = bt & 255;
        float4 v = *(const float4*)(x + (size_t)e * 4);
        unsigned* dst = g_xfrag + (size_t)t * (Bsz * Hd);
        dst[frag_idx(b, n + 0)] = f2tf(v.x);
        dst[frag_idx(b, n + 1)] = f2tf(v.y);
        dst[frag_idx(b, n + 2)] = f2tf(v.z);
        dst[frag_idx(b, n + 3)] = f2tf(v.w);
    }
}

// ---------------------------------------------------------------------------
// Persistent kernel. Grid = 128 blocks x 512 threads, 1 block/SM.
//   part = bid/32: 0=Gh0 [A], 1=Gi1 [B], 2=Gh1 [B], 3=Gp=x_p@Wi0 [A]
//   sub = bid%32: tile = sub>>1 (N-tile of 64), ks = sub&1 (K-half of 512).
// Decoupled flow sync:
//   A-group (parts 0,3; 64 blocks): phases 0..Tt-1.
//     entry:   barA >= 64*p         (all A epilogues of p-1)
//     pre-epi: barB >= 64*(p-1)     (p>=2; WAR on h0frag parity buffer)
//   B-group (parts 1,2; 64 blocks): phases 1..Tt.
//     entry:   barA >= 64*p AND barB >= 64*(p-1)
// Weights once in 128KB fragment-ready smem. A-fragments via __ldcg depth-8;
// part-3 fully L2-prefetches its next-phase x slice (2048 lines).
// ---------------------------------------------------------------------------
extern __shared__ unsigned Bw[];   // [64 k8][8 ntile][32 lane][2 reg] = 131072 B

__global__ __launch_bounds__(512, 1) void persistent_kernel(
    const float* __restrict__ Wi, const float* __restrict__ bi,
    const float* __restrict__ Wh, const float* __restrict__ bh,
    float* __restrict__ out)
{
    const int part = blockIdx.x >> 5;     // 0..3
    const int sub  = blockIdx.x & 31;
    const int tile = sub >> 1;
    const int ks   = sub & 1;
    const bool isA = (part == 0 || part == 3);

    const int tid  = threadIdx.x;
    const int lane = tid & 31;
    const int wid  = tid >> 5;
    const int wm   = wid & 7;             // M-tile (16 rows)
    const int wn   = wid >> 3;            // N-group (32 cols)
    const int n0   = tile * 64;
    const int kstart = ks * 512;

    const float* wbase = (part == 0) ? Wh
                       : (part == 1) ? Wi + (size_t)Hd * Hd
                       : (part == 2) ? Wh + (size_t)Hd * Hd
                                     : Wi;

    // ---- one-time weight preload into fragment-ready smem ----
#pragma unroll 4
    for (int i = 0; i < 16; i++) {
        int idx = tid + 512 * i;
        int krow = idx >> 4;
        int c4   = idx & 15;
        float4 w = *(const float4*)(wbase + (size_t)(kstart + krow) * Hd + n0 + c4 * 4);
        int k8 = krow >> 3, kk = krow & 7, ntile = c4 >> 1;
        int base = ((k8 * 8 + ntile) * 32 + (c4 & 1) * 16 + (kk & 3)) * 2 + (kk >> 2);
        Bw[base +  0] = f2tf(w.x);
        Bw[base +  8] = f2tf(w.y);
        Bw[base + 16] = f2tf(w.z);
        Bw[base + 24] = f2tf(w.w);
    }
    __syncthreads();

    float* mp = g_part[(part == 3) ? (6 + ks) : (part * 2 + ks)];

    const int pstart = isA ? 0 : 1;
    const int pend   = isA ? Tt - 1 : Tt;

    for (int p = pstart; p <= pend; ++p) {
        // ---- entry flow wait ----
        if (tid == 0) {
            if (isA) {
                if (p > 0)
                    while (ld_acq(&g_barA) < 64 * p) __nanosleep(64);
            } else {
                while (ld_acq(&g_barA) < 64 * p) __nanosleep(64);
                if (p > 1)
                    while (ld_acq(&g_barB) < 64 * (p - 1)) __nanosleep(64);
            }
        }
        __syncthreads();

        const unsigned* afrag =
            (part == 0) ? g_h0frag[(p - 1) & 1] :
            (part == 1) ? g_h0frag[(p - 1) & 1] :
            (part == 2) ? g_h1frag[p & 1]
                        : g_xfrag + (size_t)p * (Bsz * Hd);
        const uint4* abase = ((const uint4*)afrag)
                             + ((size_t)(ks * 64) * 8 + wm) * 32 + lane;

        float c[4][4];
#pragma unroll
        for (int nt = 0; nt < 4; nt++)
#pragma unroll
            for (int r = 0; r < 4; r++) c[nt][r] = 0.0f;

        uint4 pa[8];
#pragma unroll
        for (int i = 0; i < 8; i++)
            pa[i] = __ldcg(abase + i * 256);

#pragma unroll 8
        for (int k8 = 0; k8 < 64; k8++) {
            uint4 a = pa[k8 & 7];
            if (k8 < 56)
                pa[k8 & 7] = __ldcg(abase + (k8 + 8) * 256);
            uint2 bfr[4];
#pragma unroll
            for (int nt = 0; nt < 4; nt++)
                bfr[nt] = *(const uint2*)&Bw[(((k8 << 3) + wn * 4 + nt) * 32 + lane) * 2];
#pragma unroll
            for (int nt = 0; nt < 4; nt++)
                MMA_TF32(c[nt], a, bfr[nt]);
        }

        // partial -> global
        {
            const int gq = lane >> 2, tq = lane & 3;
#pragma unroll
            for (int nt = 0; nt < 4; nt++) {
                int row = wm * 16 + gq;
                int col = n0 + wn * 32 + nt * 8 + 2 * tq;
                *(float2*)&mp[(size_t)row * Hd + col] =
                    make_float2(c[nt][0], c[nt][1]);
                *(float2*)&mp[(size_t)(row + 8) * Hd + col] =
                    make_float2(c[nt][2], c[nt][3]);
            }
        }

        // full L2 prefetch of next-phase x slice (part 3): 2048 lines of 128B
        if (part == 3 && p + 1 < Tt) {
            const char* nx = (const char*)(g_xfrag
                              + (size_t)(p + 1) * (Bsz * Hd) + (size_t)ks * 65536);
#pragma unroll
            for (int i = 0; i < 4; i++)
                prefetchL2(nx + ((size_t)tid + i * 512) * 128);
        }

        // tile sync (4 contributors) + A's WAR wait, then epilogue
        __threadfence();
        __syncthreads();
        if (tid == 0) {
            int* cnt = isA ? &g_cntA[tile] : &g_cntB[tile];
            atomicAdd(cnt, 1);
            const int tgt = isA ? 4 * (p + 1) : 4 * p;
            while (ld_acq(cnt) < tgt) __nanosleep(64);
            if (isA && p >= 2)
                while (ld_acq(&g_barB) < 64 * (p - 1)) __nanosleep(64);
        }
        __syncthreads();

        // distributed epilogue: 4 blocks/tile, each 32 rows x 64 cols
        const int chunk = isA ? ((part == 0 ? 0 : 2) + ks)
                              : ((part - 1) * 2 + ks);
        const int row = chunk * 32 + (tid >> 4);
        const int n   = n0 + (tid & 15) * 4;
        if (isA) {
            unsigned* dstf = g_h0frag[p & 1];
            float4 a = __ldcg((const float4*)&g_part[0][(size_t)row * Hd + n]);
            float4 b = __ldcg((const float4*)&g_part[1][(size_t)row * Hd + n]);
            float4 q = __ldcg((const float4*)&g_part[6][(size_t)row * Hd + n]);
            float4 s = __ldcg((const float4*)&g_part[7][(size_t)row * Hd + n]);
            float4 b1 = *(const float4*)&bi[n];
            float4 b2 = *(const float4*)&bh[n];
            float r0 = tanhf(a.x + b.x + q.x + s.x + b1.x + b2.x);
            float r1 = tanhf(a.y + b.y + q.y + s.y + b1.y + b2.y);
            float r2 = tanhf(a.z + b.z + q.z + s.z + b1.z + b2.z);
            float r3 = tanhf(a.w + b.w + q.w + s.w + b1.w + b2.w);
            if (p == Tt - 1)
                *(float4*)&g_h0f[(size_t)row * Hd + n] = make_float4(r0, r1, r2, r3);
            dstf[frag_idx(row, n + 0)] = f2tf(r0);
            dstf[frag_idx(row, n + 1)] = f2tf(r1);
            dstf[frag_idx(row, n + 2)] = f2tf(r2);
            dstf[frag_idx(row, n + 3)] = f2tf(r3);
        } else {
            const int tt = p - 1;
            unsigned* dstf = g_h1frag[(p - 1) & 1];
            float4 s2 = __ldcg((const float4*)&g_part[2][(size_t)row * Hd + n]);
            float4 s3 = __ldcg((const float4*)&g_part[3][(size_t)row * Hd + n]);
            float4 s4 = __ldcg((const float4*)&g_part[4][(size_t)row * Hd + n]);
            float4 s5 = __ldcg((const float4*)&g_part[5][(size_t)row * Hd + n]);
            float4 b1 = *(const float4*)&bi[Hd + n];
            float4 b2 = *(const float4*)&bh[Hd + n];
            float r0 = tanhf(s2.x + s3.x + s4.x + s5.x + b1.x + b2.x);
            float r1 = tanhf(s2.y + s3.y + s4.y + s5.y + b1.y + b2.y);
            float r2 = tanhf(s2.z + s3.z + s4.z + s5.z + b1.z + b2.z);
            float r3 = tanhf(s2.w + s3.w + s4.w + s5.w + b1.w + b2.w);
            *(float4*)&out[((size_t)row * Tt + tt) * Hd + n] =
                make_float4(r0, r1, r2, r3);
            dstf[frag_idx(row, n + 0)] = f2tf(r0);
            dstf[frag_idx(row, n + 1)] = f2tf(r1);
            dstf[frag_idx(row, n + 2)] = f2tf(r2);
            dstf[frag_idx(row, n + 3)] = f2tf(r3);
        }

        // group phase arrival
        __threadfence();
        __syncthreads();
        if (tid == 0)
            atomicAdd(isA ? &g_barA : &g_barB, 1);
    }
}

// ---------------------------------------------------------------------------
// Finalize: h_n[b][0] = h0_{T-1}, h_n[b][1] = h1_{T-1} (= out[:,T-1,:])
// ---------------------------------------------------------------------------
__global__ void finalize_kernel(float* __restrict__ out)
{
    int idx = blockIdx.x * blockDim.x + threadIdx.x;
    if (idx >= Bsz * Hd) return;
    int b = idx / Hd, h = idx % Hd;
    float* hn = out + (size_t)BT * Hd;
    hn[((size_t)b * 2 + 0) * Hd + h] = g_h0f[(size_t)b * Hd + h];
    hn[((size_t)b * 2 + 1) * Hd + h] = out[((size_t)b * Tt + (Tt - 1)) * Hd + h];
}

// ---------------------------------------------------------------------------
extern "C" void kernel_launch(void* const* d_in, const int* in_sizes, int n_in,
                              void* d_out, int out_size)
{
    const float* x    = (const float*)d_in[0];   // [B,T,H]
    const float* h0in = (const float*)d_in[1];   // [1,L,H]
    const float* Wi   = (const float*)d_in[2];   // [L,H,H]
    const float* bi   = (const float*)d_in[3];   // [L,H]
    const float* Wh   = (const float*)d_in[4];   // [L,H,H]
    const float* bh   = (const float*)d_in[5];   // [L,H]
    float* out = (float*)d_out;                  // [B,T,H] then [B,L,H]

    init_kernel<<<256, 256>>>(h0in);
    xprep_kernel<<<8192, 256>>>(x);

    cudaFuncSetAttribute(persistent_kernel,
                         cudaFuncAttributeMaxDynamicSharedMemorySize, 131072);
    persistent_kernel<<<128, 512, 131072>>>(Wi, bi, Wh, bh, out);

    finalize_kernel<<<(Bsz * Hd + 255) / 256, 256>>>(out);
}